// round 1
// baseline (speedup 1.0000x reference)
#include <cuda_runtime.h>
#include <math.h>
#include <stdint.h>

// ---------------------------------------------------------------------------
// VQ-VAE forward, fp32 direct convolutions with smem tiling.
// B=64, encoder: 128x128x3 -> 32x32x128 -> VQ(512 codes, D=64) -> decoder.
// Output layout (float32, 3145732 elems):
//   [0]                 e_and_q = 1.25 * mse
//   [1 .. 3145728]      x_recon (64,3,128,128) NCHW
//   [3145729]           e_latent_loss = mse
//   [3145730]           q_latent_loss = mse
//   [3145731]           est_words = 2^entropy_bits
// ---------------------------------------------------------------------------

#define BATCH 64
#define VQ_K 512
#define VQ_D 64
#define OUT_RECON_OFF 1
#define OUT_RECON_N   (64*3*128*128)
#define OUT_ELQ  (OUT_RECON_OFF + OUT_RECON_N)      // 3145729
#define OUT_QLQ  (OUT_ELQ + 1)
#define OUT_EW   (OUT_QLQ + 1)

// ---------------- scratch buffers (static device memory, no allocs) --------
__device__ float g_h1 [64*64*64*64];   // 16.7M floats (conv1 out / tc1 out)
__device__ float g_a  [64*128*32*32];  // 8.4M
__device__ float g_b  [64*128*32*32];  // 8.4M
__device__ float g_mid[64*64*32*32];   // 4.2M (res-block mid, 64ch)
__device__ float g_ze [64*64*32*32];   // encoder latents
__device__ float g_zq [64*64*32*32];   // quantized latents
__device__ int   g_hist[VQ_K];
__device__ float g_mse[1];

// ---------------------------------------------------------------------------
// reset accumulators (graph replays must be deterministic)
// ---------------------------------------------------------------------------
__global__ void reset_k(int* hist, float* mse) {
    int t = threadIdx.x;
    if (t < VQ_K) hist[t] = 0;
    if (t == 0)   mse[0] = 0.f;
}

// ---------------------------------------------------------------------------
// 3x3 stride-1 pad-1 conv on 32x32 images.
// grid(COUT/4, B), block 128. Thread tile: 2 oh x 4 ow x 4 oc.
// ---------------------------------------------------------------------------
template<int CIN, int COUT, bool PRE, bool POST, bool BIAS>
__global__ void __launch_bounds__(128) conv3x3_k(
    const float* __restrict__ in, const float* __restrict__ w,
    const float* __restrict__ bias, float* __restrict__ out)
{
    const int n   = blockIdx.y;
    const int oc0 = blockIdx.x * 4;
    const int tid = threadIdx.x;
    const int oh0 = (tid >> 3) * 2;
    const int ow0 = (tid & 7) * 4;

    __shared__ float s_in[34 * 34];
    __shared__ float s_w[36];

    float acc[4][2][4];
#pragma unroll
    for (int a = 0; a < 4; a++)
#pragma unroll
        for (int p = 0; p < 2; p++)
#pragma unroll
            for (int q = 0; q < 4; q++) acc[a][p][q] = 0.f;

    const float* inp = in + (size_t)n * CIN * 1024;

    for (int ci = 0; ci < CIN; ci++) {
        __syncthreads();
        for (int idx = tid; idx < 34 * 34; idx += 128) {
            int r = idx / 34, c = idx - r * 34;
            int ih = r - 1, iw = c - 1;
            float v = 0.f;
            if ((unsigned)ih < 32u && (unsigned)iw < 32u)
                v = inp[ci * 1024 + ih * 32 + iw];
            if (PRE) v = fmaxf(v, 0.f);
            s_in[idx] = v;
        }
        if (tid < 36) {
            int oc = tid / 9, t = tid - oc * 9;
            s_w[tid] = w[((oc0 + oc) * CIN + ci) * 9 + t];
        }
        __syncthreads();

        float xr[4][6];
#pragma unroll
        for (int r = 0; r < 4; r++)
#pragma unroll
            for (int c = 0; c < 6; c++)
                xr[r][c] = s_in[(oh0 + r) * 34 + ow0 + c];

#pragma unroll
        for (int oc = 0; oc < 4; oc++)
#pragma unroll
            for (int kh = 0; kh < 3; kh++)
#pragma unroll
                for (int kw = 0; kw < 3; kw++) {
                    float wv = s_w[oc * 9 + kh * 3 + kw];
#pragma unroll
                    for (int ph = 0; ph < 2; ph++)
#pragma unroll
                        for (int pw = 0; pw < 4; pw++)
                            acc[oc][ph][pw] =
                                fmaf(xr[ph + kh][pw + kw], wv, acc[oc][ph][pw]);
                }
    }

#pragma unroll
    for (int oc = 0; oc < 4; oc++) {
        float bv = BIAS ? bias[oc0 + oc] : 0.f;
#pragma unroll
        for (int ph = 0; ph < 2; ph++)
#pragma unroll
            for (int pw = 0; pw < 4; pw++) {
                float v = acc[oc][ph][pw] + bv;
                if (POST) v = fmaxf(v, 0.f);
                out[((size_t)(n * COUT + oc0 + oc)) * 1024 +
                    (oh0 + ph) * 32 + (ow0 + pw)] = v;
            }
    }
}

// ---------------------------------------------------------------------------
// 4x4 stride-2 pad-1 conv. Output tile 32x32 per block.
// grid(COUT/4, (HOUT/32)^2, B), block 128. Thread tile 2x4 pos x 4 oc.
// ---------------------------------------------------------------------------
template<int CIN, int COUT, int HIN, int HOUT, bool POST>
__global__ void __launch_bounds__(128) conv4x4s2_k(
    const float* __restrict__ in, const float* __restrict__ w,
    const float* __restrict__ bias, float* __restrict__ out)
{
    const int n   = blockIdx.z;
    const int oc0 = blockIdx.x * 4;
    const int TB  = HOUT / 32;
    const int r0  = (blockIdx.y / TB) * 32;
    const int c0  = (blockIdx.y % TB) * 32;
    const int tid = threadIdx.x;
    const int loh0 = (tid >> 3) * 2;
    const int low0 = (tid & 7) * 4;

    __shared__ float s_in[66 * 66];
    __shared__ float s_w[64];

    float acc[4][2][4];
#pragma unroll
    for (int a = 0; a < 4; a++)
#pragma unroll
        for (int p = 0; p < 2; p++)
#pragma unroll
            for (int q = 0; q < 4; q++) acc[a][p][q] = 0.f;

    const int ihb = 2 * r0 - 1, iwb = 2 * c0 - 1;
    const float* inp = in + (size_t)n * CIN * HIN * HIN;

    for (int ci = 0; ci < CIN; ci++) {
        __syncthreads();
        for (int idx = tid; idx < 66 * 66; idx += 128) {
            int r = idx / 66, c = idx - r * 66;
            int ih = ihb + r, iw = iwb + c;
            float v = 0.f;
            if ((unsigned)ih < (unsigned)HIN && (unsigned)iw < (unsigned)HIN)
                v = inp[(size_t)ci * HIN * HIN + ih * HIN + iw];
            s_in[idx] = v;
        }
        if (tid < 64)
            s_w[tid] = w[((oc0 + (tid >> 4)) * CIN + ci) * 16 + (tid & 15)];
        __syncthreads();

#pragma unroll
        for (int kh = 0; kh < 4; kh++) {
            float ra[10], rb[10];
            const int rrA = 2 * loh0 + kh;
            const int base = 2 * low0;
#pragma unroll
            for (int c = 0; c < 10; c++) {
                ra[c] = s_in[rrA * 66 + base + c];
                rb[c] = s_in[(rrA + 2) * 66 + base + c];
            }
#pragma unroll
            for (int oc = 0; oc < 4; oc++)
#pragma unroll
                for (int kw = 0; kw < 4; kw++) {
                    float wv = s_w[oc * 16 + kh * 4 + kw];
#pragma unroll
                    for (int pw = 0; pw < 4; pw++) {
                        acc[oc][0][pw] = fmaf(ra[2 * pw + kw], wv, acc[oc][0][pw]);
                        acc[oc][1][pw] = fmaf(rb[2 * pw + kw], wv, acc[oc][1][pw]);
                    }
                }
        }
    }

#pragma unroll
    for (int oc = 0; oc < 4; oc++) {
        float bv = bias[oc0 + oc];
#pragma unroll
        for (int ph = 0; ph < 2; ph++)
#pragma unroll
            for (int pw = 0; pw < 4; pw++) {
                float v = acc[oc][ph][pw] + bv;
                if (POST) v = fmaxf(v, 0.f);
                out[((size_t)(n * COUT + oc0 + oc)) * HOUT * HOUT +
                    (r0 + loh0 + ph) * HOUT + (c0 + low0 + pw)] = v;
            }
    }
}

// ---------------------------------------------------------------------------
// 1x1 conv on 32x32 images (flat P=1024). grid(COUT/4, B), block 256,
// thread tile 4 positions x 4 oc. Optional residual add (res == out buffer).
// ---------------------------------------------------------------------------
template<int CIN, int COUT, bool PRE, bool BIAS, bool ADDRES>
__global__ void __launch_bounds__(256) conv1x1_k(
    const float* __restrict__ in, const float* __restrict__ w,
    const float* __restrict__ bias, float* __restrict__ out)
{
    const int n   = blockIdx.y;
    const int oc0 = blockIdx.x * 4;
    const int tid = threadIdx.x;
    const int hw0 = tid * 4;

    __shared__ float s_w[4 * CIN];
    for (int i = tid; i < 4 * CIN; i += 256)
        s_w[i] = w[(oc0 + i / CIN) * CIN + (i % CIN)];
    __syncthreads();

    float acc[4][4];
#pragma unroll
    for (int a = 0; a < 4; a++)
#pragma unroll
        for (int q = 0; q < 4; q++) acc[a][q] = 0.f;

    const float* inp = in + (size_t)n * CIN * 1024 + hw0;
    for (int ci = 0; ci < CIN; ci++) {
        float4 v = *reinterpret_cast<const float4*>(inp + (size_t)ci * 1024);
        if (PRE) {
            v.x = fmaxf(v.x, 0.f); v.y = fmaxf(v.y, 0.f);
            v.z = fmaxf(v.z, 0.f); v.w = fmaxf(v.w, 0.f);
        }
#pragma unroll
        for (int oc = 0; oc < 4; oc++) {
            float wv = s_w[oc * CIN + ci];
            acc[oc][0] = fmaf(v.x, wv, acc[oc][0]);
            acc[oc][1] = fmaf(v.y, wv, acc[oc][1]);
            acc[oc][2] = fmaf(v.z, wv, acc[oc][2]);
            acc[oc][3] = fmaf(v.w, wv, acc[oc][3]);
        }
    }

#pragma unroll
    for (int oc = 0; oc < 4; oc++) {
        float bv = BIAS ? bias[oc0 + oc] : 0.f;
        float* op = out + ((size_t)(n * COUT + oc0 + oc)) * 1024 + hw0;
        float4 o;
        o.x = acc[oc][0] + bv; o.y = acc[oc][1] + bv;
        o.z = acc[oc][2] + bv; o.w = acc[oc][3] + bv;
        if (ADDRES) {
            float4 r = *reinterpret_cast<const float4*>(op);
            o.x += r.x; o.y += r.y; o.z += r.z; o.w += r.w;
        }
        *reinterpret_cast<float4*>(op) = o;
    }
}

// ---------------------------------------------------------------------------
// ConvTranspose2d k=4 s=2 p=1 (torch weight layout (CIN,COUT,4,4)).
// out[n,co,oh,ow] = b + sum_{ci,kh,kw: (oh+1-kh) even, ih=(oh+1-kh)/2 in range}
//                     x[n,ci,ih,iw] * w[ci,co,kh,kw]
// grid(COUT/OCB, (HOUT/32)^2, B), block 128, thread tile 2x4 pos x OCB oc.
// ---------------------------------------------------------------------------
template<int CIN, int COUT, int OCB, int HIN, int HOUT, bool PRE, bool POST>
__global__ void __launch_bounds__(128) convT4x4s2_k(
    const float* __restrict__ in, const float* __restrict__ w,
    const float* __restrict__ bias, float* __restrict__ out)
{
    const int n   = blockIdx.z;
    const int oc0 = blockIdx.x * OCB;
    const int TB  = HOUT / 32;
    const int r0  = (blockIdx.y / TB) * 32;
    const int c0  = (blockIdx.y % TB) * 32;
    const int tid = threadIdx.x;
    const int loh0 = (tid >> 3) * 2;
    const int low0 = (tid & 7) * 4;

    __shared__ float s_in[18 * 18];
    __shared__ float s_w[OCB * 16];

    float acc[OCB][2][4];
#pragma unroll
    for (int a = 0; a < OCB; a++)
#pragma unroll
        for (int p = 0; p < 2; p++)
#pragma unroll
            for (int q = 0; q < 4; q++) acc[a][p][q] = 0.f;

    const int ihb = (r0 - 2) / 2;   // r0 multiple of 32 -> exact
    const int iwb = (c0 - 2) / 2;
    const float* inp = in + (size_t)n * CIN * HIN * HIN;

    for (int ci = 0; ci < CIN; ci++) {
        __syncthreads();
        for (int idx = tid; idx < 18 * 18; idx += 128) {
            int r = idx / 18, c = idx - r * 18;
            int ih = ihb + r, iw = iwb + c;
            float v = 0.f;
            if ((unsigned)ih < (unsigned)HIN && (unsigned)iw < (unsigned)HIN)
                v = inp[(size_t)ci * HIN * HIN + ih * HIN + iw];
            if (PRE) v = fmaxf(v, 0.f);
            s_in[idx] = v;
        }
        if (tid < OCB * 16)
            s_w[tid] = w[((size_t)ci * COUT + oc0 + (tid >> 4)) * 16 + (tid & 15)];
        __syncthreads();

#pragma unroll
        for (int ph = 0; ph < 2; ph++) {
            const int khb = (ph + 1) & 1;           // parity of oh == parity of ph
            const int ohg = r0 + loh0 + ph;
#pragma unroll
            for (int kh2 = 0; kh2 < 2; kh2++) {
                const int kh  = khb + 2 * kh2;
                const int ihl = ((ohg + 1 - kh) >> 1) - ihb;
                float wr[OCB][4];
#pragma unroll
                for (int oc = 0; oc < OCB; oc++)
#pragma unroll
                    for (int kw = 0; kw < 4; kw++)
                        wr[oc][kw] = s_w[oc * 16 + kh * 4 + kw];
#pragma unroll
                for (int pw = 0; pw < 4; pw++) {
                    const int kwb = (pw + 1) & 1;
                    const int owg = c0 + low0 + pw;
#pragma unroll
                    for (int kw2 = 0; kw2 < 2; kw2++) {
                        const int kw  = kwb + 2 * kw2;
                        const int iwl = ((owg + 1 - kw) >> 1) - iwb;
                        const float xv = s_in[ihl * 18 + iwl];
#pragma unroll
                        for (int oc = 0; oc < OCB; oc++)
                            acc[oc][ph][pw] = fmaf(xv, wr[oc][kw], acc[oc][ph][pw]);
                    }
                }
            }
        }
    }

#pragma unroll
    for (int oc = 0; oc < OCB; oc++) {
        float bv = bias[oc0 + oc];
#pragma unroll
        for (int ph = 0; ph < 2; ph++)
#pragma unroll
            for (int pw = 0; pw < 4; pw++) {
                float v = acc[oc][ph][pw] + bv;
                if (POST) v = fmaxf(v, 0.f);
                out[((size_t)(n * COUT + oc0 + oc)) * HOUT * HOUT +
                    (r0 + loh0 + ph) * HOUT + (c0 + low0 + pw)] = v;
            }
    }
}

// ---------------------------------------------------------------------------
// Vector quantizer: per position argmin over 512 codes (D=64), materialize
// Zq (NCHW), shared-memory histogram, block-reduced MSE.
// grid(256), block 256, dyn smem: E(32768f) + Esq(512f) + hist(512i) + red(256f)
// ---------------------------------------------------------------------------
#define VQ_SMEM ((32768 + 512 + 512 + 256) * 4)

__global__ void __launch_bounds__(256) vq_k(
    const float* __restrict__ ze, const float* __restrict__ E,
    float* __restrict__ zq, int* __restrict__ hist, float* __restrict__ mse)
{
    extern __shared__ float sm[];
    float* sE   = sm;                 // 32768
    float* sEsq = sm + 32768;         // 512
    int*   sHist= (int*)(sm + 33280); // 512
    float* sRed = sm + 33792;         // 256

    const int tid = threadIdx.x;
    for (int i = tid; i < VQ_K * VQ_D; i += 256) sE[i] = E[i];
    for (int i = tid; i < VQ_K; i += 256) sHist[i] = 0;
    __syncthreads();
    for (int i = tid; i < VQ_K; i += 256) {
        const float* e = &sE[i * VQ_D];
        float s = 0.f;
#pragma unroll 16
        for (int d = 0; d < VQ_D; d++) s = fmaf(e[d], e[d], s);
        sEsq[i] = s;
    }
    __syncthreads();

    const int p  = blockIdx.x * 256 + tid;
    const int n  = p >> 10;
    const int hw = p & 1023;
    const float* zp = ze + (size_t)n * VQ_D * 1024 + hw;

    float f[VQ_D];
#pragma unroll
    for (int d = 0; d < VQ_D; d++) f[d] = zp[(size_t)d * 1024];

    float best = 3.4e38f;
    int   bi   = 0;
    for (int k = 0; k < VQ_K; k++) {
        const float4* e4 = reinterpret_cast<const float4*>(&sE[k * VQ_D]);
        float s0 = 0.f, s1 = 0.f, s2 = 0.f, s3 = 0.f;
#pragma unroll
        for (int d = 0; d < VQ_D / 4; d++) {
            float4 e = e4[d];
            s0 = fmaf(e.x, f[4 * d + 0], s0);
            s1 = fmaf(e.y, f[4 * d + 1], s1);
            s2 = fmaf(e.z, f[4 * d + 2], s2);
            s3 = fmaf(e.w, f[4 * d + 3], s3);
        }
        float score = sEsq[k] - 2.f * ((s0 + s1) + (s2 + s3));
        if (score < best) { best = score; bi = k; }
    }

    // exact min distance + Zq write
    const float* eb = &sE[bi * VQ_D];
    float* zqp = zq + (size_t)n * VQ_D * 1024 + hw;
    float md = 0.f;
#pragma unroll
    for (int d = 0; d < VQ_D; d++) {
        float ev = eb[d];
        float dd = f[d] - ev;
        md = fmaf(dd, dd, md);
        zqp[(size_t)d * 1024] = ev;
    }

    atomicAdd(&sHist[bi], 1);
    sRed[tid] = md;
    __syncthreads();
    for (int s = 128; s > 0; s >>= 1) {
        if (tid < s) sRed[tid] += sRed[tid + s];
        __syncthreads();
    }
    if (tid == 0) atomicAdd(mse, sRed[0]);
    for (int i = tid; i < VQ_K; i += 256) {
        int c = sHist[i];
        if (c) atomicAdd(&hist[i], c);
    }
}

// ---------------------------------------------------------------------------
// Scalar outputs: losses + codebook-usage entropy.
// ---------------------------------------------------------------------------
__global__ void finalize_k(const int* __restrict__ hist,
                           const float* __restrict__ mse,
                           float* __restrict__ out)
{
    __shared__ float red[VQ_K];
    const int k = threadIdx.x;
    float pb = (float)hist[k] * (1.f / 65536.f);
    red[k] = pb * log2f(pb + 1e-10f);
    __syncthreads();
    for (int s = 256; s > 0; s >>= 1) {
        if (k < s) red[k] += red[k + s];
        __syncthreads();
    }
    if (k == 0) {
        float H = -red[0];
        float m = mse[0] * (1.f / (65536.f * 64.f));
        out[0]       = 1.25f * m;   // q + BETA*e
        out[OUT_ELQ] = m;
        out[OUT_QLQ] = m;
        out[OUT_EW]  = exp2f(H);
    }
}

// ---------------------------------------------------------------------------
// Launch
// ---------------------------------------------------------------------------
extern "C" void kernel_launch(void* const* d_in, const int* in_sizes, int n_in,
                              void* d_out, int out_size)
{
    (void)in_sizes; (void)n_in; (void)out_size;
    const float* x          = (const float*)d_in[0];
    const float* enc_w1     = (const float*)d_in[1];
    const float* enc_b1     = (const float*)d_in[2];
    const float* enc_w2     = (const float*)d_in[3];
    const float* enc_b2     = (const float*)d_in[4];
    const float* enc_w3     = (const float*)d_in[5];
    const float* enc_b3     = (const float*)d_in[6];
    const float* enc_w4     = (const float*)d_in[7];
    const float* enc_b4     = (const float*)d_in[8];
    const float* enc_res_w1 = (const float*)d_in[9];   // (2,64,128,3,3)
    const float* enc_res_w2 = (const float*)d_in[10];  // (2,128,64,1,1)
    const float* enc_adj_w  = (const float*)d_in[11];
    const float* enc_adj_b  = (const float*)d_in[12];
    const float* E          = (const float*)d_in[13];
    const float* dec_adj_w  = (const float*)d_in[14];
    const float* dec_adj_b  = (const float*)d_in[15];
    const float* dec_res_w1 = (const float*)d_in[16];
    const float* dec_res_w2 = (const float*)d_in[17];
    const float* tc1_w      = (const float*)d_in[18];
    const float* tc1_b      = (const float*)d_in[19];
    const float* tc2_w      = (const float*)d_in[20];
    const float* tc2_b      = (const float*)d_in[21];
    float* out = (float*)d_out;

    float *h1, *a, *b, *mid, *ze, *zq, *mse; int* hist;
    cudaGetSymbolAddress((void**)&h1,  g_h1);
    cudaGetSymbolAddress((void**)&a,   g_a);
    cudaGetSymbolAddress((void**)&b,   g_b);
    cudaGetSymbolAddress((void**)&mid, g_mid);
    cudaGetSymbolAddress((void**)&ze,  g_ze);
    cudaGetSymbolAddress((void**)&zq,  g_zq);
    cudaGetSymbolAddress((void**)&mse, g_mse);
    cudaGetSymbolAddress((void**)&hist, g_hist);

    cudaFuncSetAttribute(vq_k, cudaFuncAttributeMaxDynamicSharedMemorySize, VQ_SMEM);

    reset_k<<<1, 512>>>(hist, mse);

    // ---- Encoder ----
    conv4x4s2_k<3, 64, 128, 64, true><<<dim3(16, 4, BATCH), 128>>>(x, enc_w1, enc_b1, h1);
    conv4x4s2_k<64, 128, 64, 32, true><<<dim3(32, 1, BATCH), 128>>>(h1, enc_w2, enc_b2, a);
    conv3x3_k<128, 128, false, true,  true><<<dim3(32, BATCH), 128>>>(a, enc_w3, enc_b3, b);
    conv3x3_k<128, 128, false, false, true><<<dim3(32, BATCH), 128>>>(b, enc_w4, enc_b4, a);
    // res block 0: mid = relu(conv3x3(relu(a))); a += conv1x1(mid)
    conv3x3_k<128, 64, true, true, false><<<dim3(16, BATCH), 128>>>(a, enc_res_w1, nullptr, mid);
    conv1x1_k<64, 128, false, false, true><<<dim3(32, BATCH), 256>>>(mid, enc_res_w2, nullptr, a);
    // res block 1
    conv3x3_k<128, 64, true, true, false><<<dim3(16, BATCH), 128>>>(a, enc_res_w1 + 64 * 128 * 9, nullptr, mid);
    conv1x1_k<64, 128, false, false, true><<<dim3(32, BATCH), 256>>>(mid, enc_res_w2 + 128 * 64, nullptr, a);
    // enc_adj (res_stack's final relu fused as PRE)
    conv1x1_k<128, 64, true, true, false><<<dim3(16, BATCH), 256>>>(a, enc_adj_w, enc_adj_b, ze);

    // ---- Vector quantizer ----
    vq_k<<<256, 256, VQ_SMEM>>>(ze, E, zq, hist, mse);
    finalize_k<<<1, 512>>>(hist, mse, out);

    // ---- Decoder ----
    conv3x3_k<64, 128, false, false, true><<<dim3(32, BATCH), 128>>>(zq, dec_adj_w, dec_adj_b, a);
    conv3x3_k<128, 64, true, true, false><<<dim3(16, BATCH), 128>>>(a, dec_res_w1, nullptr, mid);
    conv1x1_k<64, 128, false, false, true><<<dim3(32, BATCH), 256>>>(mid, dec_res_w2, nullptr, a);
    conv3x3_k<128, 64, true, true, false><<<dim3(16, BATCH), 128>>>(a, dec_res_w1 + 64 * 128 * 9, nullptr, mid);
    conv1x1_k<64, 128, false, false, true><<<dim3(32, BATCH), 256>>>(mid, dec_res_w2 + 128 * 64, nullptr, a);
    // tc1 (res_stack final relu fused as PRE), output relu
    convT4x4s2_k<128, 64, 4, 32, 64, true, true><<<dim3(16, 4, BATCH), 128>>>(a, tc1_w, tc1_b, h1);
    // tc2 -> x_recon directly into d_out
    convT4x4s2_k<64, 3, 3, 64, 128, false, false><<<dim3(1, 16, BATCH), 128>>>(h1, tc2_w, tc2_b, out + OUT_RECON_OFF);
}

// round 2
// speedup vs baseline: 1.0446x; 1.0446x over previous
#include <cuda_runtime.h>
#include <math.h>
#include <stdint.h>

// ---------------------------------------------------------------------------
// VQ-VAE forward, fp32 direct convolutions with smem tiling.
// B=64, encoder: 128x128x3 -> 32x32x128 -> VQ(512 codes, D=64) -> decoder.
// Output layout (float32, 3145732 elems):
//   [0]                 e_and_q = 1.25 * mse
//   [1 .. 3145728]      x_recon (64,3,128,128) NCHW
//   [3145729]           e_latent_loss = mse
//   [3145730]           q_latent_loss = mse
//   [3145731]           est_words = 2^entropy_bits
// ---------------------------------------------------------------------------

#define BATCH 64
#define VQ_K 512
#define VQ_D 64
#define OUT_RECON_OFF 1
#define OUT_RECON_N   (64*3*128*128)
#define OUT_ELQ  (OUT_RECON_OFF + OUT_RECON_N)      // 3145729
#define OUT_QLQ  (OUT_ELQ + 1)
#define OUT_EW   (OUT_QLQ + 1)

// ---------------- scratch buffers (static device memory, no allocs) --------
__device__ float g_h1 [64*64*64*64];   // 16.7M floats (conv1 out / tc1 out)
__device__ float g_a  [64*128*32*32];  // 8.4M
__device__ float g_b  [64*128*32*32];  // 8.4M
__device__ float g_mid[64*64*32*32];   // 4.2M (res-block mid, 64ch)
__device__ float g_ze [64*64*32*32];   // encoder latents
__device__ float g_zq [64*64*32*32];   // quantized latents
__device__ int   g_hist[VQ_K];
__device__ float g_mse[1];

// ---------------------------------------------------------------------------
// reset accumulators (graph replays must be deterministic)
// ---------------------------------------------------------------------------
__global__ void reset_k(int* hist, float* mse) {
    int t = threadIdx.x;
    if (t < VQ_K) hist[t] = 0;
    if (t == 0)   mse[0] = 0.f;
}

// ---------------------------------------------------------------------------
// 3x3 stride-1 pad-1 conv on 32x32 images.
// grid(COUT/4, B), block 128. Thread tile: 2 oh x 4 ow x 4 oc.
// ---------------------------------------------------------------------------
template<int CIN, int COUT, bool PRE, bool POST, bool BIAS>
__global__ void __launch_bounds__(128) conv3x3_k(
    const float* __restrict__ in, const float* __restrict__ w,
    const float* __restrict__ bias, float* __restrict__ out)
{
    const int n   = blockIdx.y;
    const int oc0 = blockIdx.x * 4;
    const int tid = threadIdx.x;
    const int oh0 = (tid >> 3) * 2;
    const int ow0 = (tid & 7) * 4;

    __shared__ float s_in[34 * 34];
    __shared__ float s_w[36];

    float acc[4][2][4];
#pragma unroll
    for (int a = 0; a < 4; a++)
#pragma unroll
        for (int p = 0; p < 2; p++)
#pragma unroll
            for (int q = 0; q < 4; q++) acc[a][p][q] = 0.f;

    const float* inp = in + (size_t)n * CIN * 1024;

    for (int ci = 0; ci < CIN; ci++) {
        __syncthreads();
        for (int idx = tid; idx < 34 * 34; idx += 128) {
            int r = idx / 34, c = idx - r * 34;
            int ih = r - 1, iw = c - 1;
            float v = 0.f;
            if ((unsigned)ih < 32u && (unsigned)iw < 32u)
                v = inp[ci * 1024 + ih * 32 + iw];
            if (PRE) v = fmaxf(v, 0.f);
            s_in[idx] = v;
        }
        if (tid < 36) {
            int oc = tid / 9, t = tid - oc * 9;
            s_w[tid] = w[((oc0 + oc) * CIN + ci) * 9 + t];
        }
        __syncthreads();

        float xr[4][6];
#pragma unroll
        for (int r = 0; r < 4; r++)
#pragma unroll
            for (int c = 0; c < 6; c++)
                xr[r][c] = s_in[(oh0 + r) * 34 + ow0 + c];

#pragma unroll
        for (int oc = 0; oc < 4; oc++)
#pragma unroll
            for (int kh = 0; kh < 3; kh++)
#pragma unroll
                for (int kw = 0; kw < 3; kw++) {
                    float wv = s_w[oc * 9 + kh * 3 + kw];
#pragma unroll
                    for (int ph = 0; ph < 2; ph++)
#pragma unroll
                        for (int pw = 0; pw < 4; pw++)
                            acc[oc][ph][pw] =
                                fmaf(xr[ph + kh][pw + kw], wv, acc[oc][ph][pw]);
                }
    }

#pragma unroll
    for (int oc = 0; oc < 4; oc++) {
        float bv = BIAS ? bias[oc0 + oc] : 0.f;
#pragma unroll
        for (int ph = 0; ph < 2; ph++)
#pragma unroll
            for (int pw = 0; pw < 4; pw++) {
                float v = acc[oc][ph][pw] + bv;
                if (POST) v = fmaxf(v, 0.f);
                out[((size_t)(n * COUT + oc0 + oc)) * 1024 +
                    (oh0 + ph) * 32 + (ow0 + pw)] = v;
            }
    }
}

// ---------------------------------------------------------------------------
// 4x4 stride-2 pad-1 conv. Output tile 32x32 per block.
// grid(COUT/4, (HOUT/32)^2, B), block 128. Thread tile 2x4 pos x 4 oc.
// ---------------------------------------------------------------------------
template<int CIN, int COUT, int HIN, int HOUT, bool POST>
__global__ void __launch_bounds__(128) conv4x4s2_k(
    const float* __restrict__ in, const float* __restrict__ w,
    const float* __restrict__ bias, float* __restrict__ out)
{
    const int n   = blockIdx.z;
    const int oc0 = blockIdx.x * 4;
    const int TB  = HOUT / 32;
    const int r0  = (blockIdx.y / TB) * 32;
    const int c0  = (blockIdx.y % TB) * 32;
    const int tid = threadIdx.x;
    const int loh0 = (tid >> 3) * 2;
    const int low0 = (tid & 7) * 4;

    __shared__ float s_in[66 * 66];
    __shared__ float s_w[64];

    float acc[4][2][4];
#pragma unroll
    for (int a = 0; a < 4; a++)
#pragma unroll
        for (int p = 0; p < 2; p++)
#pragma unroll
            for (int q = 0; q < 4; q++) acc[a][p][q] = 0.f;

    const int ihb = 2 * r0 - 1, iwb = 2 * c0 - 1;
    const float* inp = in + (size_t)n * CIN * HIN * HIN;

    for (int ci = 0; ci < CIN; ci++) {
        __syncthreads();
        for (int idx = tid; idx < 66 * 66; idx += 128) {
            int r = idx / 66, c = idx - r * 66;
            int ih = ihb + r, iw = iwb + c;
            float v = 0.f;
            if ((unsigned)ih < (unsigned)HIN && (unsigned)iw < (unsigned)HIN)
                v = inp[(size_t)ci * HIN * HIN + ih * HIN + iw];
            s_in[idx] = v;
        }
        if (tid < 64)
            s_w[tid] = w[((oc0 + (tid >> 4)) * CIN + ci) * 16 + (tid & 15)];
        __syncthreads();

#pragma unroll
        for (int kh = 0; kh < 4; kh++) {
            float ra[10], rb[10];
            const int rrA = 2 * loh0 + kh;
            const int base = 2 * low0;
#pragma unroll
            for (int c = 0; c < 10; c++) {
                ra[c] = s_in[rrA * 66 + base + c];
                rb[c] = s_in[(rrA + 2) * 66 + base + c];
            }
#pragma unroll
            for (int oc = 0; oc < 4; oc++)
#pragma unroll
                for (int kw = 0; kw < 4; kw++) {
                    float wv = s_w[oc * 16 + kh * 4 + kw];
#pragma unroll
                    for (int pw = 0; pw < 4; pw++) {
                        acc[oc][0][pw] = fmaf(ra[2 * pw + kw], wv, acc[oc][0][pw]);
                        acc[oc][1][pw] = fmaf(rb[2 * pw + kw], wv, acc[oc][1][pw]);
                    }
                }
        }
    }

#pragma unroll
    for (int oc = 0; oc < 4; oc++) {
        float bv = bias[oc0 + oc];
#pragma unroll
        for (int ph = 0; ph < 2; ph++)
#pragma unroll
            for (int pw = 0; pw < 4; pw++) {
                float v = acc[oc][ph][pw] + bv;
                if (POST) v = fmaxf(v, 0.f);
                out[((size_t)(n * COUT + oc0 + oc)) * HOUT * HOUT +
                    (r0 + loh0 + ph) * HOUT + (c0 + low0 + pw)] = v;
            }
    }
}

// ---------------------------------------------------------------------------
// 1x1 conv on 32x32 images (flat P=1024). grid(COUT/4, B), block 256,
// thread tile 4 positions x 4 oc. Optional residual add (res == out buffer).
// ---------------------------------------------------------------------------
template<int CIN, int COUT, bool PRE, bool BIAS, bool ADDRES>
__global__ void __launch_bounds__(256) conv1x1_k(
    const float* __restrict__ in, const float* __restrict__ w,
    const float* __restrict__ bias, float* __restrict__ out)
{
    const int n   = blockIdx.y;
    const int oc0 = blockIdx.x * 4;
    const int tid = threadIdx.x;
    const int hw0 = tid * 4;

    __shared__ float s_w[4 * CIN];
    for (int i = tid; i < 4 * CIN; i += 256)
        s_w[i] = w[(oc0 + i / CIN) * CIN + (i % CIN)];
    __syncthreads();

    float acc[4][4];
#pragma unroll
    for (int a = 0; a < 4; a++)
#pragma unroll
        for (int q = 0; q < 4; q++) acc[a][q] = 0.f;

    const float* inp = in + (size_t)n * CIN * 1024 + hw0;
    for (int ci = 0; ci < CIN; ci++) {
        float4 v = *reinterpret_cast<const float4*>(inp + (size_t)ci * 1024);
        if (PRE) {
            v.x = fmaxf(v.x, 0.f); v.y = fmaxf(v.y, 0.f);
            v.z = fmaxf(v.z, 0.f); v.w = fmaxf(v.w, 0.f);
        }
#pragma unroll
        for (int oc = 0; oc < 4; oc++) {
            float wv = s_w[oc * CIN + ci];
            acc[oc][0] = fmaf(v.x, wv, acc[oc][0]);
            acc[oc][1] = fmaf(v.y, wv, acc[oc][1]);
            acc[oc][2] = fmaf(v.z, wv, acc[oc][2]);
            acc[oc][3] = fmaf(v.w, wv, acc[oc][3]);
        }
    }

#pragma unroll
    for (int oc = 0; oc < 4; oc++) {
        float bv = BIAS ? bias[oc0 + oc] : 0.f;
        float* op = out + ((size_t)(n * COUT + oc0 + oc)) * 1024 + hw0;
        float4 o;
        o.x = acc[oc][0] + bv; o.y = acc[oc][1] + bv;
        o.z = acc[oc][2] + bv; o.w = acc[oc][3] + bv;
        if (ADDRES) {
            float4 r = *reinterpret_cast<const float4*>(op);
            o.x += r.x; o.y += r.y; o.z += r.z; o.w += r.w;
        }
        *reinterpret_cast<float4*>(op) = o;
    }
}

// ---------------------------------------------------------------------------
// ConvTranspose2d k=4 s=2 p=1 (torch weight layout (CIN,COUT,4,4)).
// out[n,co,oh,ow] = b + sum_{ci,kh,kw: (oh+1-kh) even, ih=(oh+1-kh)/2 in range}
//                     x[n,ci,ih,iw] * w[ci,co,kh,kw]
// grid(COUT/OCB, (HOUT/32)^2, B), block 128, thread tile 2x4 pos x OCB oc.
// ---------------------------------------------------------------------------
template<int CIN, int COUT, int OCB, int HIN, int HOUT, bool PRE, bool POST>
__global__ void __launch_bounds__(128) convT4x4s2_k(
    const float* __restrict__ in, const float* __restrict__ w,
    const float* __restrict__ bias, float* __restrict__ out)
{
    const int n   = blockIdx.z;
    const int oc0 = blockIdx.x * OCB;
    const int TB  = HOUT / 32;
    const int r0  = (blockIdx.y / TB) * 32;
    const int c0  = (blockIdx.y % TB) * 32;
    const int tid = threadIdx.x;
    const int loh0 = (tid >> 3) * 2;
    const int low0 = (tid & 7) * 4;

    __shared__ float s_in[18 * 18];
    __shared__ float s_w[OCB * 16];

    float acc[OCB][2][4];
#pragma unroll
    for (int a = 0; a < OCB; a++)
#pragma unroll
        for (int p = 0; p < 2; p++)
#pragma unroll
            for (int q = 0; q < 4; q++) acc[a][p][q] = 0.f;

    const int ihb = (r0 - 2) / 2;   // r0 multiple of 32 -> exact
    const int iwb = (c0 - 2) / 2;
    const float* inp = in + (size_t)n * CIN * HIN * HIN;

    for (int ci = 0; ci < CIN; ci++) {
        __syncthreads();
        for (int idx = tid; idx < 18 * 18; idx += 128) {
            int r = idx / 18, c = idx - r * 18;
            int ih = ihb + r, iw = iwb + c;
            float v = 0.f;
            if ((unsigned)ih < (unsigned)HIN && (unsigned)iw < (unsigned)HIN)
                v = inp[(size_t)ci * HIN * HIN + ih * HIN + iw];
            if (PRE) v = fmaxf(v, 0.f);
            s_in[idx] = v;
        }
        if (tid < OCB * 16)
            s_w[tid] = w[((size_t)ci * COUT + oc0 + (tid >> 4)) * 16 + (tid & 15)];
        __syncthreads();

#pragma unroll
        for (int ph = 0; ph < 2; ph++) {
            const int khb = (ph + 1) & 1;           // parity of oh == parity of ph
            const int ohg = r0 + loh0 + ph;
#pragma unroll
            for (int kh2 = 0; kh2 < 2; kh2++) {
                const int kh  = khb + 2 * kh2;
                const int ihl = ((ohg + 1 - kh) >> 1) - ihb;
                float wr[OCB][4];
#pragma unroll
                for (int oc = 0; oc < OCB; oc++)
#pragma unroll
                    for (int kw = 0; kw < 4; kw++)
                        wr[oc][kw] = s_w[oc * 16 + kh * 4 + kw];
#pragma unroll
                for (int pw = 0; pw < 4; pw++) {
                    const int kwb = (pw + 1) & 1;
                    const int owg = c0 + low0 + pw;
#pragma unroll
                    for (int kw2 = 0; kw2 < 2; kw2++) {
                        const int kw  = kwb + 2 * kw2;
                        const int iwl = ((owg + 1 - kw) >> 1) - iwb;
                        const float xv = s_in[ihl * 18 + iwl];
#pragma unroll
                        for (int oc = 0; oc < OCB; oc++)
                            acc[oc][ph][pw] = fmaf(xv, wr[oc][kw], acc[oc][ph][pw]);
                    }
                }
            }
        }
    }

#pragma unroll
    for (int oc = 0; oc < OCB; oc++) {
        float bv = bias[oc0 + oc];
#pragma unroll
        for (int ph = 0; ph < 2; ph++)
#pragma unroll
            for (int pw = 0; pw < 4; pw++) {
                float v = acc[oc][ph][pw] + bv;
                if (POST) v = fmaxf(v, 0.f);
                out[((size_t)(n * COUT + oc0 + oc)) * HOUT * HOUT +
                    (r0 + loh0 + ph) * HOUT + (c0 + low0 + pw)] = v;
            }
    }
}

// ---------------------------------------------------------------------------
// Vector quantizer: per position argmin over 512 codes (D=64), materialize
// Zq (NCHW), shared-memory histogram, block-reduced MSE.
// grid(256), block 256, dyn smem: E(32768f) + Esq(512f) + hist(512i) + red(256f)
// ---------------------------------------------------------------------------
#define VQ_SMEM ((32768 + 512 + 512 + 256) * 4)

__global__ void __launch_bounds__(256) vq_k(
    const float* __restrict__ ze, const float* __restrict__ E,
    float* __restrict__ zq, int* __restrict__ hist, float* __restrict__ mse)
{
    extern __shared__ float sm[];
    float* sE   = sm;                 // 32768
    float* sEsq = sm + 32768;         // 512
    int*   sHist= (int*)(sm + 33280); // 512
    float* sRed = sm + 33792;         // 256

    const int tid = threadIdx.x;
    for (int i = tid; i < VQ_K * VQ_D; i += 256) sE[i] = E[i];
    for (int i = tid; i < VQ_K; i += 256) sHist[i] = 0;
    __syncthreads();
    for (int i = tid; i < VQ_K; i += 256) {
        const float* e = &sE[i * VQ_D];
        float s = 0.f;
#pragma unroll 16
        for (int d = 0; d < VQ_D; d++) s = fmaf(e[d], e[d], s);
        sEsq[i] = s;
    }
    __syncthreads();

    const int p  = blockIdx.x * 256 + tid;
    const int n  = p >> 10;
    const int hw = p & 1023;
    const float* zp = ze + (size_t)n * VQ_D * 1024 + hw;

    float f[VQ_D];
#pragma unroll
    for (int d = 0; d < VQ_D; d++) f[d] = zp[(size_t)d * 1024];

    float best = 3.4e38f;
    int   bi   = 0;
    for (int k = 0; k < VQ_K; k++) {
        const float4* e4 = reinterpret_cast<const float4*>(&sE[k * VQ_D]);
        float s0 = 0.f, s1 = 0.f, s2 = 0.f, s3 = 0.f;
#pragma unroll
        for (int d = 0; d < VQ_D / 4; d++) {
            float4 e = e4[d];
            s0 = fmaf(e.x, f[4 * d + 0], s0);
            s1 = fmaf(e.y, f[4 * d + 1], s1);
            s2 = fmaf(e.z, f[4 * d + 2], s2);
            s3 = fmaf(e.w, f[4 * d + 3], s3);
        }
        float score = sEsq[k] - 2.f * ((s0 + s1) + (s2 + s3));
        if (score < best) { best = score; bi = k; }
    }

    // exact min distance + Zq write
    const float* eb = &sE[bi * VQ_D];
    float* zqp = zq + (size_t)n * VQ_D * 1024 + hw;
    float md = 0.f;
#pragma unroll
    for (int d = 0; d < VQ_D; d++) {
        float ev = eb[d];
        float dd = f[d] - ev;
        md = fmaf(dd, dd, md);
        zqp[(size_t)d * 1024] = ev;
    }

    atomicAdd(&sHist[bi], 1);
    sRed[tid] = md;
    __syncthreads();
    for (int s = 128; s > 0; s >>= 1) {
        if (tid < s) sRed[tid] += sRed[tid + s];
        __syncthreads();
    }
    if (tid == 0) atomicAdd(mse, sRed[0]);
    for (int i = tid; i < VQ_K; i += 256) {
        int c = sHist[i];
        if (c) atomicAdd(&hist[i], c);
    }
}

// ---------------------------------------------------------------------------
// Scalar outputs: losses + codebook-usage entropy.
// ---------------------------------------------------------------------------
__global__ void finalize_k(const int* __restrict__ hist,
                           const float* __restrict__ mse,
                           float* __restrict__ out)
{
    __shared__ float red[VQ_K];
    const int k = threadIdx.x;
    float pb = (float)hist[k] * (1.f / 65536.f);
    red[k] = pb * log2f(pb + 1e-10f);
    __syncthreads();
    for (int s = 256; s > 0; s >>= 1) {
        if (k < s) red[k] += red[k + s];
        __syncthreads();
    }
    if (k == 0) {
        float H = -red[0];
        float m = mse[0] * (1.f / (65536.f * 64.f));
        out[0]       = 1.25f * m;   // q + BETA*e
        out[OUT_ELQ] = m;
        out[OUT_QLQ] = m;
        out[OUT_EW]  = exp2f(H);
    }
}

// ---------------------------------------------------------------------------
// Launch
// ---------------------------------------------------------------------------
extern "C" void kernel_launch(void* const* d_in, const int* in_sizes, int n_in,
                              void* d_out, int out_size)
{
    (void)in_sizes; (void)n_in; (void)out_size;
    const float* x          = (const float*)d_in[0];
    const float* enc_w1     = (const float*)d_in[1];
    const float* enc_b1     = (const float*)d_in[2];
    const float* enc_w2     = (const float*)d_in[3];
    const float* enc_b2     = (const float*)d_in[4];
    const float* enc_w3     = (const float*)d_in[5];
    const float* enc_b3     = (const float*)d_in[6];
    const float* enc_w4     = (const float*)d_in[7];
    const float* enc_b4     = (const float*)d_in[8];
    const float* enc_res_w1 = (const float*)d_in[9];   // (2,64,128,3,3)
    const float* enc_res_w2 = (const float*)d_in[10];  // (2,128,64,1,1)
    const float* enc_adj_w  = (const float*)d_in[11];
    const float* enc_adj_b  = (const float*)d_in[12];
    const float* E          = (const float*)d_in[13];
    const float* dec_adj_w  = (const float*)d_in[14];
    const float* dec_adj_b  = (const float*)d_in[15];
    const float* dec_res_w1 = (const float*)d_in[16];
    const float* dec_res_w2 = (const float*)d_in[17];
    const float* tc1_w      = (const float*)d_in[18];
    const float* tc1_b      = (const float*)d_in[19];
    const float* tc2_w      = (const float*)d_in[20];
    const float* tc2_b      = (const float*)d_in[21];
    float* out = (float*)d_out;

    float *h1, *a, *b, *mid, *ze, *zq, *mse; int* hist;
    cudaGetSymbolAddress((void**)&h1,  g_h1);
    cudaGetSymbolAddress((void**)&a,   g_a);
    cudaGetSymbolAddress((void**)&b,   g_b);
    cudaGetSymbolAddress((void**)&mid, g_mid);
    cudaGetSymbolAddress((void**)&ze,  g_ze);
    cudaGetSymbolAddress((void**)&zq,  g_zq);
    cudaGetSymbolAddress((void**)&mse, g_mse);
    cudaGetSymbolAddress((void**)&hist, g_hist);

    cudaFuncSetAttribute(vq_k, cudaFuncAttributeMaxDynamicSharedMemorySize, VQ_SMEM);

    reset_k<<<1, 512>>>(hist, mse);

    // ---- Encoder ----
    conv4x4s2_k<3, 64, 128, 64, true><<<dim3(16, 4, BATCH), 128>>>(x, enc_w1, enc_b1, h1);
    conv4x4s2_k<64, 128, 64, 32, true><<<dim3(32, 1, BATCH), 128>>>(h1, enc_w2, enc_b2, a);
    conv3x3_k<128, 128, false, true,  true><<<dim3(32, BATCH), 128>>>(a, enc_w3, enc_b3, b);
    conv3x3_k<128, 128, false, false, true><<<dim3(32, BATCH), 128>>>(b, enc_w4, enc_b4, a);
    // res block 0: mid = relu(conv3x3(relu(a))); a += conv1x1(mid)
    conv3x3_k<128, 64, true, true, false><<<dim3(16, BATCH), 128>>>(a, enc_res_w1, nullptr, mid);
    conv1x1_k<64, 128, false, false, true><<<dim3(32, BATCH), 256>>>(mid, enc_res_w2, nullptr, a);
    // res block 1
    conv3x3_k<128, 64, true, true, false><<<dim3(16, BATCH), 128>>>(a, enc_res_w1 + 64 * 128 * 9, nullptr, mid);
    conv1x1_k<64, 128, false, false, true><<<dim3(32, BATCH), 256>>>(mid, enc_res_w2 + 128 * 64, nullptr, a);
    // enc_adj (res_stack's final relu fused as PRE)
    conv1x1_k<128, 64, true, true, false><<<dim3(16, BATCH), 256>>>(a, enc_adj_w, enc_adj_b, ze);

    // ---- Vector quantizer ----
    vq_k<<<256, 256, VQ_SMEM>>>(ze, E, zq, hist, mse);
    finalize_k<<<1, 512>>>(hist, mse, out);

    // ---- Decoder ----
    conv3x3_k<64, 128, false, false, true><<<dim3(32, BATCH), 128>>>(zq, dec_adj_w, dec_adj_b, a);
    conv3x3_k<128, 64, true, true, false><<<dim3(16, BATCH), 128>>>(a, dec_res_w1, nullptr, mid);
    conv1x1_k<64, 128, false, false, true><<<dim3(32, BATCH), 256>>>(mid, dec_res_w2, nullptr, a);
    conv3x3_k<128, 64, true, true, false><<<dim3(16, BATCH), 128>>>(a, dec_res_w1 + 64 * 128 * 9, nullptr, mid);
    conv1x1_k<64, 128, false, false, true><<<dim3(32, BATCH), 256>>>(mid, dec_res_w2 + 128 * 64, nullptr, a);
    // tc1 (res_stack final relu fused as PRE), output relu
    convT4x4s2_k<128, 64, 4, 32, 64, true, true><<<dim3(16, 4, BATCH), 128>>>(a, tc1_w, tc1_b, h1);
    // tc2 -> x_recon directly into d_out
    convT4x4s2_k<64, 3, 3, 64, 128, false, false><<<dim3(1, 16, BATCH), 128>>>(h1, tc2_w, tc2_b, out + OUT_RECON_OFF);
}

// round 3
// speedup vs baseline: 1.0658x; 1.0203x over previous
#include <cuda_runtime.h>
#include <math.h>
#include <stdint.h>

// ---------------------------------------------------------------------------
// VQ-VAE forward, fp32 with packed f32x2 FFMA2 convolutions.
// Output layout (float32, 3145732 elems):
//   [0] e_and_q  [1..3145728] x_recon  [3145729] e_latent  [3145730] q_latent
//   [3145731] est_words
// ---------------------------------------------------------------------------

#define BATCH 64
#define VQ_K 512
#define VQ_D 64
#define OUT_RECON_OFF 1
#define OUT_RECON_N   (64*3*128*128)
#define OUT_ELQ  (OUT_RECON_OFF + OUT_RECON_N)
#define OUT_QLQ  (OUT_ELQ + 1)
#define OUT_EW   (OUT_QLQ + 1)

typedef unsigned long long ull;

// ---- packed f32x2 helpers --------------------------------------------------
__device__ __forceinline__ ull pk2(float lo, float hi) {
    ull r; asm("mov.b64 %0, {%1, %2};" : "=l"(r) : "f"(lo), "f"(hi)); return r;
}
__device__ __forceinline__ float2 unpk(ull v) {
    float2 r; asm("mov.b64 {%0, %1}, %2;" : "=f"(r.x), "=f"(r.y) : "l"(v)); return r;
}
__device__ __forceinline__ void fma2(ull& d, ull a, ull b) {
    asm("fma.rn.f32x2 %0, %1, %2, %0;" : "+l"(d) : "l"(a), "l"(b));
}

// ---------------- scratch buffers -------------------------------------------
__device__ float g_h1 [64*64*64*64];
__device__ float g_a  [64*128*32*32];
__device__ float g_b  [64*128*32*32];
__device__ float g_mid[64*64*32*32];
__device__ float g_ze [64*64*32*32];
__device__ float g_zq [64*64*32*32];
__device__ int   g_hist[VQ_K];
__device__ float g_mse[1];

__global__ void reset_k(int* hist, float* mse) {
    int t = threadIdx.x;
    if (t < VQ_K) hist[t] = 0;
    if (t == 0)   mse[0] = 0.f;
}

// ---------------------------------------------------------------------------
// 3x3 stride-1 pad-1 conv on 32x32 images, f32x2 packed.
// grid(COUT/4, B), block 128. Thread tile 2oh x 4ow x 4oc; lanes = pw pairs.
// Weights for all ci preloaded & duplicated in smem; input double-buffered.
// ---------------------------------------------------------------------------
template<int CIN, int COUT, bool PRE, bool POST, bool BIAS>
__global__ void __launch_bounds__(128, 4) conv3x3_k(
    const float* __restrict__ in, const float* __restrict__ w,
    const float* __restrict__ bias, float* __restrict__ out)
{
    const int n   = blockIdx.y;
    const int oc0 = blockIdx.x * 4;
    const int tid = threadIdx.x;
    const int oh0 = (tid >> 3) * 2;
    const int ow0 = (tid & 7) * 4;

    __shared__ float s_in[2][34 * 34];
    __shared__ ull   s_w2[CIN * 4 * 9];   // [ci][oc][kk], lanes duplicated

    // preload all weights (coalesced src), duplicate into both lanes
    for (int i = tid; i < 4 * CIN * 9; i += 128) {
        int oc = i / (CIN * 9);
        int r  = i - oc * (CIN * 9);
        int ci = r / 9, kk = r - ci * 9;
        float v = w[(size_t)(oc0 + oc) * CIN * 9 + r];
        s_w2[(ci * 4 + oc) * 9 + kk] = pk2(v, v);
    }

    // precompute staging gmem offsets (within one channel plane), -1 = pad
    int goff[10];
#pragma unroll
    for (int s = 0; s < 10; s++) {
        int idx = tid + s * 128;
        int r = idx / 34, c = idx - r * 34;
        int ih = r - 1, iw = c - 1;
        goff[s] = ((unsigned)ih < 32u && (unsigned)iw < 32u) ? ih * 32 + iw : -1;
    }
    const float* inp = in + (size_t)n * CIN * 1024;

    // stage ci = 0
    {
        float* b0 = s_in[0];
#pragma unroll
        for (int s = 0; s < 9; s++) {
            float v = (goff[s] >= 0) ? inp[goff[s]] : 0.f;
            if (PRE) v = fmaxf(v, 0.f);
            b0[tid + s * 128] = v;
        }
        if (tid < 4) {
            float v = (goff[9] >= 0) ? inp[goff[9]] : 0.f;
            if (PRE) v = fmaxf(v, 0.f);
            b0[tid + 1152] = v;
        }
    }
    __syncthreads();

    ull acc[4][2][2];
#pragma unroll
    for (int a = 0; a < 4; a++)
#pragma unroll
        for (int p = 0; p < 2; p++) { acc[a][p][0] = 0ULL; acc[a][p][1] = 0ULL; }

    for (int ci = 0; ci < CIN; ci++) {
        const float* cur = s_in[ci & 1];

        // prefetch next channel into the other buffer
        if (ci + 1 < CIN) {
            const float* inn = inp + (size_t)(ci + 1) * 1024;
            float* nb = s_in[(ci + 1) & 1];
#pragma unroll
            for (int s = 0; s < 9; s++) {
                float v = (goff[s] >= 0) ? inn[goff[s]] : 0.f;
                if (PRE) v = fmaxf(v, 0.f);
                nb[tid + s * 128] = v;
            }
            if (tid < 4) {
                float v = (goff[9] >= 0) ? inn[goff[9]] : 0.f;
                if (PRE) v = fmaxf(v, 0.f);
                nb[tid + 1152] = v;
            }
        }

        // input pairs: rows oh0..oh0+3, cols ow0..ow0+5
        ull Ar[4][3], Mr[4][2];
#pragma unroll
        for (int r = 0; r < 4; r++) {
            const float* p = cur + (oh0 + r) * 34 + ow0;
            float x0 = p[0], x1 = p[1], x2 = p[2], x3 = p[3], x4 = p[4], x5 = p[5];
            Ar[r][0] = pk2(x0, x1); Ar[r][1] = pk2(x2, x3); Ar[r][2] = pk2(x4, x5);
            Mr[r][0] = pk2(x1, x2); Mr[r][1] = pk2(x3, x4);
        }

        const ull* wci = s_w2 + ci * 36;
#pragma unroll
        for (int oc = 0; oc < 4; oc++)
#pragma unroll
            for (int kh = 0; kh < 3; kh++)
#pragma unroll
                for (int kw = 0; kw < 3; kw++) {
                    ull w2 = wci[oc * 9 + kh * 3 + kw];
#pragma unroll
                    for (int ph = 0; ph < 2; ph++) {
                        int r = ph + kh;
                        ull p0 = (kw == 0) ? Ar[r][0] : ((kw == 1) ? Mr[r][0] : Ar[r][1]);
                        ull p1 = (kw == 0) ? Ar[r][1] : ((kw == 1) ? Mr[r][1] : Ar[r][2]);
                        fma2(acc[oc][ph][0], p0, w2);
                        fma2(acc[oc][ph][1], p1, w2);
                    }
                }
        __syncthreads();
    }

#pragma unroll
    for (int oc = 0; oc < 4; oc++) {
        float bv = BIAS ? bias[oc0 + oc] : 0.f;
        float* orow = out + ((size_t)(n * COUT + oc0 + oc)) * 1024 + oh0 * 32 + ow0;
#pragma unroll
        for (int ph = 0; ph < 2; ph++)
#pragma unroll
            for (int j = 0; j < 2; j++) {
                float2 v = unpk(acc[oc][ph][j]);
                v.x += bv; v.y += bv;
                if (POST) { v.x = fmaxf(v.x, 0.f); v.y = fmaxf(v.y, 0.f); }
                *reinterpret_cast<float2*>(orow + ph * 32 + 2 * j) = v;
            }
    }
}

// ---------------------------------------------------------------------------
// 4x4 stride-2 pad-1 conv, f32x2 packed (lanes = oh pair).
// grid(COUT/4, (HOUT/32)^2, B), block 128. Dynamic smem:
//   [ull w2: CIN*4*16][float in: 2 x 66*66]
// ---------------------------------------------------------------------------
template<int CIN, int COUT, int HIN, int HOUT, bool POST>
__global__ void __launch_bounds__(128, 3) conv4x4s2_k(
    const float* __restrict__ in, const float* __restrict__ w,
    const float* __restrict__ bias, float* __restrict__ out)
{
    extern __shared__ char dsm[];
    ull*   s_w2  = (ull*)dsm;
    float* s_in0 = (float*)(dsm + (size_t)CIN * 4 * 16 * 8);
    float* s_in1 = s_in0 + 66 * 66;

    const int n   = blockIdx.z;
    const int oc0 = blockIdx.x * 4;
    const int TB  = HOUT / 32;
    const int r0  = (blockIdx.y / TB) * 32;
    const int c0  = (blockIdx.y % TB) * 32;
    const int tid = threadIdx.x;
    const int loh0 = (tid >> 3) * 2;
    const int low0 = (tid & 7) * 4;

    // preload duplicated weights
    for (int i = tid; i < 4 * CIN * 16; i += 128) {
        int oc = i / (CIN * 16);
        int r  = i - oc * (CIN * 16);
        int ci = r / 16, kk = r - ci * 16;
        float v = w[(size_t)(oc0 + oc) * CIN * 16 + r];
        s_w2[(ci * 4 + oc) * 16 + kk] = pk2(v, v);
    }

    const int ihb = 2 * r0 - 1, iwb = 2 * c0 - 1;
    const float* inp = in + (size_t)n * CIN * HIN * HIN;

    // stage ci = 0
    for (int idx = tid; idx < 66 * 66; idx += 128) {
        int r = idx / 66, c = idx - r * 66;
        int ih = ihb + r, iw = iwb + c;
        float v = 0.f;
        if ((unsigned)ih < (unsigned)HIN && (unsigned)iw < (unsigned)HIN)
            v = inp[(size_t)ih * HIN + iw];
        s_in0[idx] = v;
    }
    __syncthreads();

    ull acc[4][4];
#pragma unroll
    for (int a = 0; a < 4; a++)
#pragma unroll
        for (int q = 0; q < 4; q++) acc[a][q] = 0ULL;

    for (int ci = 0; ci < CIN; ci++) {
        const float* cur = (ci & 1) ? s_in1 : s_in0;
        if (ci + 1 < CIN) {
            float* nb = ((ci + 1) & 1) ? s_in1 : s_in0;
            const float* inn = inp + (size_t)(ci + 1) * HIN * HIN;
            for (int idx = tid; idx < 66 * 66; idx += 128) {
                int r = idx / 66, c = idx - r * 66;
                int ih = ihb + r, iw = iwb + c;
                float v = 0.f;
                if ((unsigned)ih < (unsigned)HIN && (unsigned)iw < (unsigned)HIN)
                    v = inn[(size_t)ih * HIN + iw];
                nb[idx] = v;
            }
        }

        const int rowA0 = 2 * loh0;
        const int base  = 2 * low0;
        const ull* wci  = s_w2 + ci * 64;
#pragma unroll
        for (int kh = 0; kh < 4; kh++) {
            const float* pa = cur + (rowA0 + kh) * 66 + base;
            const float* pb = pa + 132;
            ull P[10];
#pragma unroll
            for (int c = 0; c < 10; c++) P[c] = pk2(pa[c], pb[c]);
#pragma unroll
            for (int oc = 0; oc < 4; oc++)
#pragma unroll
                for (int kw = 0; kw < 4; kw++) {
                    ull w2 = wci[oc * 16 + kh * 4 + kw];
#pragma unroll
                    for (int pw = 0; pw < 4; pw++)
                        fma2(acc[oc][pw], P[2 * pw + kw], w2);
                }
        }
        __syncthreads();
    }

#pragma unroll
    for (int oc = 0; oc < 4; oc++) {
        float bv = bias[oc0 + oc];
        float* obase = out + ((size_t)(n * COUT + oc0 + oc)) * HOUT * HOUT +
                       (size_t)(r0 + loh0) * HOUT + (c0 + low0);
#pragma unroll
        for (int pw = 0; pw < 4; pw++) {
            float2 v = unpk(acc[oc][pw]);
            v.x += bv; v.y += bv;
            if (POST) { v.x = fmaxf(v.x, 0.f); v.y = fmaxf(v.y, 0.f); }
            obase[pw]        = v.x;
            obase[HOUT + pw] = v.y;
        }
    }
}

// ---------------------------------------------------------------------------
// ConvTranspose2d k=4 s=2 p=1 (torch layout (CIN,COUT,4,4)), f32x2 packed.
// Lanes = (oh even, oh odd). For a fixed input column iw and kw tap, the two
// output rows consume rows {ih0,ih0+1} (kh 1/0) and {ih0-1,ih0} (kh 3/2), so
// weights are pre-paired {w[kh_odd],w[kh_even]} in smem.
// grid(COUT/OCB, (HOUT/32)^2, B), block 128.
// ---------------------------------------------------------------------------
template<int CIN, int COUT, int OCB, int HIN, int HOUT, bool PRE, bool POST>
__global__ void __launch_bounds__(128, 4) convT4x4s2_k(
    const float* __restrict__ in, const float* __restrict__ w,
    const float* __restrict__ bias, float* __restrict__ out)
{
    const int n   = blockIdx.z;
    const int oc0 = blockIdx.x * OCB;
    const int TB  = HOUT / 32;
    const int r0  = (blockIdx.y / TB) * 32;
    const int c0  = (blockIdx.y % TB) * 32;
    const int tid = threadIdx.x;
    const int loh0 = (tid >> 3) * 2;
    const int low0 = (tid & 7) * 4;

    __shared__ float s_in[2][18 * 18];
    __shared__ ull   s_w2[CIN * OCB * 8];   // [ci][oc][kw][pair]

    // preload paired weights: pair0 = {w[1][kw], w[0][kw]}, pair1 = {w[3][kw], w[2][kw]}
    for (int i = tid; i < CIN * OCB * 8; i += 128) {
        int per = OCB * 8;
        int ci = i / per;
        int r  = i - ci * per;
        int oc = r >> 3;
        int t  = r & 7;
        int kw = t >> 1, p = t & 1;
        const float* wb = w + ((size_t)ci * COUT + oc0 + oc) * 16;
        s_w2[i] = pk2(wb[(p * 2 + 1) * 4 + kw], wb[(p * 2) * 4 + kw]);
    }

    const int ihb = (r0 - 2) / 2;
    const int iwb = (c0 - 2) / 2;
    const float* inp = in + (size_t)n * CIN * HIN * HIN;

    int goff[3];
#pragma unroll
    for (int s = 0; s < 3; s++) {
        int idx = tid + s * 128;
        int r = idx / 18, c = idx - r * 18;
        int ih = ihb + r, iw = iwb + c;
        goff[s] = ((unsigned)ih < (unsigned)HIN && (unsigned)iw < (unsigned)HIN)
                      ? ih * HIN + iw : -1;
    }

    // stage ci = 0
    {
        float* b0 = s_in[0];
#pragma unroll
        for (int s = 0; s < 2; s++) {
            float v = (goff[s] >= 0) ? inp[goff[s]] : 0.f;
            if (PRE) v = fmaxf(v, 0.f);
            b0[tid + s * 128] = v;
        }
        if (tid < 68) {
            float v = (goff[2] >= 0) ? inp[goff[2]] : 0.f;
            if (PRE) v = fmaxf(v, 0.f);
            b0[tid + 256] = v;
        }
    }
    __syncthreads();

    ull acc[OCB][4];
#pragma unroll
    for (int a = 0; a < OCB; a++)
#pragma unroll
        for (int q = 0; q < 4; q++) acc[a][q] = 0ULL;

    const int rb = loh0 >> 1;   // local row of ih0-1
    const int cb = low0 >> 1;   // local col base

    for (int ci = 0; ci < CIN; ci++) {
        const float* cur = s_in[ci & 1];
        if (ci + 1 < CIN) {
            const float* inn = inp + (size_t)(ci + 1) * HIN * HIN;
            float* nb = s_in[(ci + 1) & 1];
#pragma unroll
            for (int s = 0; s < 2; s++) {
                float v = (goff[s] >= 0) ? inn[goff[s]] : 0.f;
                if (PRE) v = fmaxf(v, 0.f);
                nb[tid + s * 128] = v;
            }
            if (tid < 68) {
                float v = (goff[2] >= 0) ? inn[goff[2]] : 0.f;
                if (PRE) v = fmaxf(v, 0.f);
                nb[tid + 256] = v;
            }
        }

        // rows ih0-1, ih0, ih0+1 at 4 columns
        ull A[4], B[4];
#pragma unroll
        for (int c = 0; c < 4; c++) {
            float x0 = cur[rb * 18 + cb + c];
            float x1 = cur[(rb + 1) * 18 + cb + c];
            float x2 = cur[(rb + 2) * 18 + cb + c];
            A[c] = pk2(x1, x2);   // lanes: (ph0 uses ih0 w/ kh1, ph1 uses ih0+1 w/ kh0)
            B[c] = pk2(x0, x1);   // lanes: (ph0 uses ih0-1 w/ kh3, ph1 uses ih0 w/ kh2)
        }

        const ull* wci = s_w2 + ci * OCB * 8;
#pragma unroll
        for (int oc = 0; oc < OCB; oc++) {
            const ull* wp = wci + oc * 8;
#pragma unroll
            for (int pw = 0; pw < 4; pw++) {
                const int kwh = (pw & 1) ? 0 : 1;
                const int rh  = (pw >> 1) + 1 + (pw & 1);
                fma2(acc[oc][pw], A[rh],     wp[kwh * 2 + 0]);
                fma2(acc[oc][pw], B[rh],     wp[kwh * 2 + 1]);
                fma2(acc[oc][pw], A[rh - 1], wp[(kwh + 2) * 2 + 0]);
                fma2(acc[oc][pw], B[rh - 1], wp[(kwh + 2) * 2 + 1]);
            }
        }
        __syncthreads();
    }

#pragma unroll
    for (int oc = 0; oc < OCB; oc++) {
        float bv = bias[oc0 + oc];
        float* obase = out + ((size_t)(n * COUT + oc0 + oc)) * HOUT * HOUT +
                       (size_t)(r0 + loh0) * HOUT + (c0 + low0);
#pragma unroll
        for (int pw = 0; pw < 4; pw++) {
            float2 v = unpk(acc[oc][pw]);
            v.x += bv; v.y += bv;
            if (POST) { v.x = fmaxf(v.x, 0.f); v.y = fmaxf(v.y, 0.f); }
            obase[pw]        = v.x;   // oh even
            obase[HOUT + pw] = v.y;   // oh odd
        }
    }
}

// ---------------------------------------------------------------------------
// 1x1 conv on 32x32 images (unchanged from passing round).
// ---------------------------------------------------------------------------
template<int CIN, int COUT, bool PRE, bool BIAS, bool ADDRES>
__global__ void __launch_bounds__(256) conv1x1_k(
    const float* __restrict__ in, const float* __restrict__ w,
    const float* __restrict__ bias, float* __restrict__ out)
{
    const int n   = blockIdx.y;
    const int oc0 = blockIdx.x * 4;
    const int tid = threadIdx.x;
    const int hw0 = tid * 4;

    __shared__ float s_w[4 * CIN];
    for (int i = tid; i < 4 * CIN; i += 256)
        s_w[i] = w[(oc0 + i / CIN) * CIN + (i % CIN)];
    __syncthreads();

    float acc[4][4];
#pragma unroll
    for (int a = 0; a < 4; a++)
#pragma unroll
        for (int q = 0; q < 4; q++) acc[a][q] = 0.f;

    const float* inp = in + (size_t)n * CIN * 1024 + hw0;
    for (int ci = 0; ci < CIN; ci++) {
        float4 v = *reinterpret_cast<const float4*>(inp + (size_t)ci * 1024);
        if (PRE) {
            v.x = fmaxf(v.x, 0.f); v.y = fmaxf(v.y, 0.f);
            v.z = fmaxf(v.z, 0.f); v.w = fmaxf(v.w, 0.f);
        }
#pragma unroll
        for (int oc = 0; oc < 4; oc++) {
            float wv = s_w[oc * CIN + ci];
            acc[oc][0] = fmaf(v.x, wv, acc[oc][0]);
            acc[oc][1] = fmaf(v.y, wv, acc[oc][1]);
            acc[oc][2] = fmaf(v.z, wv, acc[oc][2]);
            acc[oc][3] = fmaf(v.w, wv, acc[oc][3]);
        }
    }

#pragma unroll
    for (int oc = 0; oc < 4; oc++) {
        float bv = BIAS ? bias[oc0 + oc] : 0.f;
        float* op = out + ((size_t)(n * COUT + oc0 + oc)) * 1024 + hw0;
        float4 o;
        o.x = acc[oc][0] + bv; o.y = acc[oc][1] + bv;
        o.z = acc[oc][2] + bv; o.w = acc[oc][3] + bv;
        if (ADDRES) {
            float4 r = *reinterpret_cast<const float4*>(op);
            o.x += r.x; o.y += r.y; o.z += r.z; o.w += r.w;
        }
        *reinterpret_cast<float4*>(op) = o;
    }
}

// ---------------------------------------------------------------------------
// Vector quantizer (unchanged from passing round).
// ---------------------------------------------------------------------------
#define VQ_SMEM ((32768 + 512 + 512 + 256) * 4)

__global__ void __launch_bounds__(256) vq_k(
    const float* __restrict__ ze, const float* __restrict__ E,
    float* __restrict__ zq, int* __restrict__ hist, float* __restrict__ mse)
{
    extern __shared__ float sm[];
    float* sE   = sm;
    float* sEsq = sm + 32768;
    int*   sHist= (int*)(sm + 33280);
    float* sRed = sm + 33792;

    const int tid = threadIdx.x;
    for (int i = tid; i < VQ_K * VQ_D; i += 256) sE[i] = E[i];
    for (int i = tid; i < VQ_K; i += 256) sHist[i] = 0;
    __syncthreads();
    for (int i = tid; i < VQ_K; i += 256) {
        const float* e = &sE[i * VQ_D];
        float s = 0.f;
#pragma unroll 16
        for (int d = 0; d < VQ_D; d++) s = fmaf(e[d], e[d], s);
        sEsq[i] = s;
    }
    __syncthreads();

    const int p  = blockIdx.x * 256 + tid;
    const int n  = p >> 10;
    const int hw = p & 1023;
    const float* zp = ze + (size_t)n * VQ_D * 1024 + hw;

    float f[VQ_D];
#pragma unroll
    for (int d = 0; d < VQ_D; d++) f[d] = zp[(size_t)d * 1024];

    float best = 3.4e38f;
    int   bi   = 0;
    for (int k = 0; k < VQ_K; k++) {
        const float4* e4 = reinterpret_cast<const float4*>(&sE[k * VQ_D]);
        float s0 = 0.f, s1 = 0.f, s2 = 0.f, s3 = 0.f;
#pragma unroll
        for (int d = 0; d < VQ_D / 4; d++) {
            float4 e = e4[d];
            s0 = fmaf(e.x, f[4 * d + 0], s0);
            s1 = fmaf(e.y, f[4 * d + 1], s1);
            s2 = fmaf(e.z, f[4 * d + 2], s2);
            s3 = fmaf(e.w, f[4 * d + 3], s3);
        }
        float score = sEsq[k] - 2.f * ((s0 + s1) + (s2 + s3));
        if (score < best) { best = score; bi = k; }
    }

    const float* eb = &sE[bi * VQ_D];
    float* zqp = zq + (size_t)n * VQ_D * 1024 + hw;
    float md = 0.f;
#pragma unroll
    for (int d = 0; d < VQ_D; d++) {
        float ev = eb[d];
        float dd = f[d] - ev;
        md = fmaf(dd, dd, md);
        zqp[(size_t)d * 1024] = ev;
    }

    atomicAdd(&sHist[bi], 1);
    sRed[tid] = md;
    __syncthreads();
    for (int s = 128; s > 0; s >>= 1) {
        if (tid < s) sRed[tid] += sRed[tid + s];
        __syncthreads();
    }
    if (tid == 0) atomicAdd(mse, sRed[0]);
    for (int i = tid; i < VQ_K; i += 256) {
        int c = sHist[i];
        if (c) atomicAdd(&hist[i], c);
    }
}

__global__ void finalize_k(const int* __restrict__ hist,
                           const float* __restrict__ mse,
                           float* __restrict__ out)
{
    __shared__ float red[VQ_K];
    const int k = threadIdx.x;
    float pb = (float)hist[k] * (1.f / 65536.f);
    red[k] = pb * log2f(pb + 1e-10f);
    __syncthreads();
    for (int s = 256; s > 0; s >>= 1) {
        if (k < s) red[k] += red[k + s];
        __syncthreads();
    }
    if (k == 0) {
        float H = -red[0];
        float m = mse[0] * (1.f / (65536.f * 64.f));
        out[0]       = 1.25f * m;
        out[OUT_ELQ] = m;
        out[OUT_QLQ] = m;
        out[OUT_EW]  = exp2f(H);
    }
}

// ---------------------------------------------------------------------------
// Launch
// ---------------------------------------------------------------------------
extern "C" void kernel_launch(void* const* d_in, const int* in_sizes, int n_in,
                              void* d_out, int out_size)
{
    (void)in_sizes; (void)n_in; (void)out_size;
    const float* x          = (const float*)d_in[0];
    const float* enc_w1     = (const float*)d_in[1];
    const float* enc_b1     = (const float*)d_in[2];
    const float* enc_w2     = (const float*)d_in[3];
    const float* enc_b2     = (const float*)d_in[4];
    const float* enc_w3     = (const float*)d_in[5];
    const float* enc_b3     = (const float*)d_in[6];
    const float* enc_w4     = (const float*)d_in[7];
    const float* enc_b4     = (const float*)d_in[8];
    const float* enc_res_w1 = (const float*)d_in[9];
    const float* enc_res_w2 = (const float*)d_in[10];
    const float* enc_adj_w  = (const float*)d_in[11];
    const float* enc_adj_b  = (const float*)d_in[12];
    const float* E          = (const float*)d_in[13];
    const float* dec_adj_w  = (const float*)d_in[14];
    const float* dec_adj_b  = (const float*)d_in[15];
    const float* dec_res_w1 = (const float*)d_in[16];
    const float* dec_res_w2 = (const float*)d_in[17];
    const float* tc1_w      = (const float*)d_in[18];
    const float* tc1_b      = (const float*)d_in[19];
    const float* tc2_w      = (const float*)d_in[20];
    const float* tc2_b      = (const float*)d_in[21];
    float* out = (float*)d_out;

    float *h1, *a, *b, *mid, *ze, *zq, *mse; int* hist;
    cudaGetSymbolAddress((void**)&h1,  g_h1);
    cudaGetSymbolAddress((void**)&a,   g_a);
    cudaGetSymbolAddress((void**)&b,   g_b);
    cudaGetSymbolAddress((void**)&mid, g_mid);
    cudaGetSymbolAddress((void**)&ze,  g_ze);
    cudaGetSymbolAddress((void**)&zq,  g_zq);
    cudaGetSymbolAddress((void**)&mse, g_mse);
    cudaGetSymbolAddress((void**)&hist, g_hist);

    cudaFuncSetAttribute(vq_k, cudaFuncAttributeMaxDynamicSharedMemorySize, VQ_SMEM);

    const int SMEM_C1 = 3  * 4 * 16 * 8 + 2 * 66 * 66 * 4;   // 36384
    const int SMEM_C2 = 64 * 4 * 16 * 8 + 2 * 66 * 66 * 4;   // 67616
    cudaFuncSetAttribute(conv4x4s2_k<3, 64, 128, 64, true>,
                         cudaFuncAttributeMaxDynamicSharedMemorySize, SMEM_C1);
    cudaFuncSetAttribute(conv4x4s2_k<64, 128, 64, 32, true>,
                         cudaFuncAttributeMaxDynamicSharedMemorySize, SMEM_C2);

    reset_k<<<1, 512>>>(hist, mse);

    // ---- Encoder ----
    conv4x4s2_k<3, 64, 128, 64, true><<<dim3(16, 4, BATCH), 128, SMEM_C1>>>(x, enc_w1, enc_b1, h1);
    conv4x4s2_k<64, 128, 64, 32, true><<<dim3(32, 1, BATCH), 128, SMEM_C2>>>(h1, enc_w2, enc_b2, a);
    conv3x3_k<128, 128, false, true,  true><<<dim3(32, BATCH), 128>>>(a, enc_w3, enc_b3, b);
    conv3x3_k<128, 128, false, false, true><<<dim3(32, BATCH), 128>>>(b, enc_w4, enc_b4, a);
    conv3x3_k<128, 64, true, true, false><<<dim3(16, BATCH), 128>>>(a, enc_res_w1, nullptr, mid);
    conv1x1_k<64, 128, false, false, true><<<dim3(32, BATCH), 256>>>(mid, enc_res_w2, nullptr, a);
    conv3x3_k<128, 64, true, true, false><<<dim3(16, BATCH), 128>>>(a, enc_res_w1 + 64 * 128 * 9, nullptr, mid);
    conv1x1_k<64, 128, false, false, true><<<dim3(32, BATCH), 256>>>(mid, enc_res_w2 + 128 * 64, nullptr, a);
    conv1x1_k<128, 64, true, true, false><<<dim3(16, BATCH), 256>>>(a, enc_adj_w, enc_adj_b, ze);

    // ---- Vector quantizer ----
    vq_k<<<256, 256, VQ_SMEM>>>(ze, E, zq, hist, mse);
    finalize_k<<<1, 512>>>(hist, mse, out);

    // ---- Decoder ----
    conv3x3_k<64, 128, false, false, true><<<dim3(32, BATCH), 128>>>(zq, dec_adj_w, dec_adj_b, a);
    conv3x3_k<128, 64, true, true, false><<<dim3(16, BATCH), 128>>>(a, dec_res_w1, nullptr, mid);
    conv1x1_k<64, 128, false, false, true><<<dim3(32, BATCH), 256>>>(mid, dec_res_w2, nullptr, a);
    conv3x3_k<128, 64, true, true, false><<<dim3(16, BATCH), 128>>>(a, dec_res_w1 + 64 * 128 * 9, nullptr, mid);
    conv1x1_k<64, 128, false, false, true><<<dim3(32, BATCH), 256>>>(mid, dec_res_w2 + 128 * 64, nullptr, a);
    convT4x4s2_k<128, 64, 4, 32, 64, true, true><<<dim3(16, 4, BATCH), 128>>>(a, tc1_w, tc1_b, h1);
    convT4x4s2_k<64, 3, 3, 64, 128, false, false><<<dim3(1, 16, BATCH), 128>>>(h1, tc2_w, tc2_b, out + OUT_RECON_OFF);
}

// round 4
// speedup vs baseline: 1.0673x; 1.0014x over previous
#include <cuda_runtime.h>
#include <math.h>
#include <stdint.h>

// ---------------------------------------------------------------------------
// VQ-VAE forward, fp32 with packed f32x2 FFMA2 convolutions.
// Output layout (float32, 3145732 elems):
//   [0] e_and_q  [1..3145728] x_recon  [3145729] e_latent  [3145730] q_latent
//   [3145731] est_words
// ---------------------------------------------------------------------------

#define BATCH 64
#define VQ_K 512
#define VQ_D 64
#define OUT_RECON_OFF 1
#define OUT_RECON_N   (64*3*128*128)
#define OUT_ELQ  (OUT_RECON_OFF + OUT_RECON_N)
#define OUT_QLQ  (OUT_ELQ + 1)
#define OUT_EW   (OUT_QLQ + 1)

typedef unsigned long long ull;

// ---- packed f32x2 helpers --------------------------------------------------
__device__ __forceinline__ ull pk2(float lo, float hi) {
    ull r; asm("mov.b64 %0, {%1, %2};" : "=l"(r) : "f"(lo), "f"(hi)); return r;
}
__device__ __forceinline__ float2 unpk(ull v) {
    float2 r; asm("mov.b64 {%0, %1}, %2;" : "=f"(r.x), "=f"(r.y) : "l"(v)); return r;
}
__device__ __forceinline__ void fma2(ull& d, ull a, ull b) {
    asm("fma.rn.f32x2 %0, %1, %2, %0;" : "+l"(d) : "l"(a), "l"(b));
}

// ---------------- scratch buffers -------------------------------------------
__device__ float g_h1 [64*64*64*64];
__device__ float g_a  [64*128*32*32];
__device__ float g_b  [64*128*32*32];
__device__ float g_mid[64*64*32*32];
__device__ float g_ze [64*64*32*32];
__device__ float g_zq [64*64*32*32];
__device__ int   g_hist[VQ_K];
__device__ float g_mse[1];

__global__ void reset_k(int* hist, float* mse) {
    int t = threadIdx.x;
    if (t < VQ_K) hist[t] = 0;
    if (t == 0)   mse[0] = 0.f;
}

// ---------------------------------------------------------------------------
// 3x3 stride-1 pad-1 conv on 32x32 images, f32x2 packed.
// grid(COUT/4, B), block 128. Thread tile 2oh x 4ow x 4oc; lanes = pw pairs.
// Weights for all ci preloaded & duplicated in smem; input double-buffered.
// ---------------------------------------------------------------------------
template<int CIN, int COUT, bool PRE, bool POST, bool BIAS>
__global__ void __launch_bounds__(128, 4) conv3x3_k(
    const float* __restrict__ in, const float* __restrict__ w,
    const float* __restrict__ bias, float* __restrict__ out)
{
    const int n   = blockIdx.y;
    const int oc0 = blockIdx.x * 4;
    const int tid = threadIdx.x;
    const int oh0 = (tid >> 3) * 2;
    const int ow0 = (tid & 7) * 4;

    __shared__ float s_in[2][34 * 34];
    __shared__ ull   s_w2[CIN * 4 * 9];   // [ci][oc][kk], lanes duplicated

    // preload all weights (coalesced src), duplicate into both lanes
    for (int i = tid; i < 4 * CIN * 9; i += 128) {
        int oc = i / (CIN * 9);
        int r  = i - oc * (CIN * 9);
        int ci = r / 9, kk = r - ci * 9;
        float v = w[(size_t)(oc0 + oc) * CIN * 9 + r];
        s_w2[(ci * 4 + oc) * 9 + kk] = pk2(v, v);
    }

    // precompute staging gmem offsets (within one channel plane), -1 = pad
    int goff[10];
#pragma unroll
    for (int s = 0; s < 10; s++) {
        int idx = tid + s * 128;
        int r = idx / 34, c = idx - r * 34;
        int ih = r - 1, iw = c - 1;
        goff[s] = ((unsigned)ih < 32u && (unsigned)iw < 32u) ? ih * 32 + iw : -1;
    }
    const float* inp = in + (size_t)n * CIN * 1024;

    // stage ci = 0
    {
        float* b0 = s_in[0];
#pragma unroll
        for (int s = 0; s < 9; s++) {
            float v = (goff[s] >= 0) ? inp[goff[s]] : 0.f;
            if (PRE) v = fmaxf(v, 0.f);
            b0[tid + s * 128] = v;
        }
        if (tid < 4) {
            float v = (goff[9] >= 0) ? inp[goff[9]] : 0.f;
            if (PRE) v = fmaxf(v, 0.f);
            b0[tid + 1152] = v;
        }
    }
    __syncthreads();

    ull acc[4][2][2];
#pragma unroll
    for (int a = 0; a < 4; a++)
#pragma unroll
        for (int p = 0; p < 2; p++) { acc[a][p][0] = 0ULL; acc[a][p][1] = 0ULL; }

    for (int ci = 0; ci < CIN; ci++) {
        const float* cur = s_in[ci & 1];

        // prefetch next channel into the other buffer
        if (ci + 1 < CIN) {
            const float* inn = inp + (size_t)(ci + 1) * 1024;
            float* nb = s_in[(ci + 1) & 1];
#pragma unroll
            for (int s = 0; s < 9; s++) {
                float v = (goff[s] >= 0) ? inn[goff[s]] : 0.f;
                if (PRE) v = fmaxf(v, 0.f);
                nb[tid + s * 128] = v;
            }
            if (tid < 4) {
                float v = (goff[9] >= 0) ? inn[goff[9]] : 0.f;
                if (PRE) v = fmaxf(v, 0.f);
                nb[tid + 1152] = v;
            }
        }

        // input pairs: rows oh0..oh0+3, cols ow0..ow0+5
        ull Ar[4][3], Mr[4][2];
#pragma unroll
        for (int r = 0; r < 4; r++) {
            const float* p = cur + (oh0 + r) * 34 + ow0;
            float x0 = p[0], x1 = p[1], x2 = p[2], x3 = p[3], x4 = p[4], x5 = p[5];
            Ar[r][0] = pk2(x0, x1); Ar[r][1] = pk2(x2, x3); Ar[r][2] = pk2(x4, x5);
            Mr[r][0] = pk2(x1, x2); Mr[r][1] = pk2(x3, x4);
        }

        const ull* wci = s_w2 + ci * 36;
#pragma unroll
        for (int oc = 0; oc < 4; oc++)
#pragma unroll
            for (int kh = 0; kh < 3; kh++)
#pragma unroll
                for (int kw = 0; kw < 3; kw++) {
                    ull w2 = wci[oc * 9 + kh * 3 + kw];
#pragma unroll
                    for (int ph = 0; ph < 2; ph++) {
                        int r = ph + kh;
                        ull p0 = (kw == 0) ? Ar[r][0] : ((kw == 1) ? Mr[r][0] : Ar[r][1]);
                        ull p1 = (kw == 0) ? Ar[r][1] : ((kw == 1) ? Mr[r][1] : Ar[r][2]);
                        fma2(acc[oc][ph][0], p0, w2);
                        fma2(acc[oc][ph][1], p1, w2);
                    }
                }
        __syncthreads();
    }

#pragma unroll
    for (int oc = 0; oc < 4; oc++) {
        float bv = BIAS ? bias[oc0 + oc] : 0.f;
        float* orow = out + ((size_t)(n * COUT + oc0 + oc)) * 1024 + oh0 * 32 + ow0;
#pragma unroll
        for (int ph = 0; ph < 2; ph++)
#pragma unroll
            for (int j = 0; j < 2; j++) {
                float2 v = unpk(acc[oc][ph][j]);
                v.x += bv; v.y += bv;
                if (POST) { v.x = fmaxf(v.x, 0.f); v.y = fmaxf(v.y, 0.f); }
                *reinterpret_cast<float2*>(orow + ph * 32 + 2 * j) = v;
            }
    }
}

// ---------------------------------------------------------------------------
// 4x4 stride-2 pad-1 conv, f32x2 packed (lanes = oh pair).
// grid(COUT/4, (HOUT/32)^2, B), block 128. Dynamic smem:
//   [ull w2: CIN*4*16][float in: 2 x 66*66]
// ---------------------------------------------------------------------------
template<int CIN, int COUT, int HIN, int HOUT, bool POST>
__global__ void __launch_bounds__(128, 3) conv4x4s2_k(
    const float* __restrict__ in, const float* __restrict__ w,
    const float* __restrict__ bias, float* __restrict__ out)
{
    extern __shared__ char dsm[];
    ull*   s_w2  = (ull*)dsm;
    float* s_in0 = (float*)(dsm + (size_t)CIN * 4 * 16 * 8);
    float* s_in1 = s_in0 + 66 * 66;

    const int n   = blockIdx.z;
    const int oc0 = blockIdx.x * 4;
    const int TB  = HOUT / 32;
    const int r0  = (blockIdx.y / TB) * 32;
    const int c0  = (blockIdx.y % TB) * 32;
    const int tid = threadIdx.x;
    const int loh0 = (tid >> 3) * 2;
    const int low0 = (tid & 7) * 4;

    // preload duplicated weights
    for (int i = tid; i < 4 * CIN * 16; i += 128) {
        int oc = i / (CIN * 16);
        int r  = i - oc * (CIN * 16);
        int ci = r / 16, kk = r - ci * 16;
        float v = w[(size_t)(oc0 + oc) * CIN * 16 + r];
        s_w2[(ci * 4 + oc) * 16 + kk] = pk2(v, v);
    }

    const int ihb = 2 * r0 - 1, iwb = 2 * c0 - 1;
    const float* inp = in + (size_t)n * CIN * HIN * HIN;

    // stage ci = 0
    for (int idx = tid; idx < 66 * 66; idx += 128) {
        int r = idx / 66, c = idx - r * 66;
        int ih = ihb + r, iw = iwb + c;
        float v = 0.f;
        if ((unsigned)ih < (unsigned)HIN && (unsigned)iw < (unsigned)HIN)
            v = inp[(size_t)ih * HIN + iw];
        s_in0[idx] = v;
    }
    __syncthreads();

    ull acc[4][4];
#pragma unroll
    for (int a = 0; a < 4; a++)
#pragma unroll
        for (int q = 0; q < 4; q++) acc[a][q] = 0ULL;

    for (int ci = 0; ci < CIN; ci++) {
        const float* cur = (ci & 1) ? s_in1 : s_in0;
        if (ci + 1 < CIN) {
            float* nb = ((ci + 1) & 1) ? s_in1 : s_in0;
            const float* inn = inp + (size_t)(ci + 1) * HIN * HIN;
            for (int idx = tid; idx < 66 * 66; idx += 128) {
                int r = idx / 66, c = idx - r * 66;
                int ih = ihb + r, iw = iwb + c;
                float v = 0.f;
                if ((unsigned)ih < (unsigned)HIN && (unsigned)iw < (unsigned)HIN)
                    v = inn[(size_t)ih * HIN + iw];
                nb[idx] = v;
            }
        }

        const int rowA0 = 2 * loh0;
        const int base  = 2 * low0;
        const ull* wci  = s_w2 + ci * 64;
#pragma unroll
        for (int kh = 0; kh < 4; kh++) {
            const float* pa = cur + (rowA0 + kh) * 66 + base;
            const float* pb = pa + 132;
            ull P[10];
#pragma unroll
            for (int c = 0; c < 10; c++) P[c] = pk2(pa[c], pb[c]);
#pragma unroll
            for (int oc = 0; oc < 4; oc++)
#pragma unroll
                for (int kw = 0; kw < 4; kw++) {
                    ull w2 = wci[oc * 16 + kh * 4 + kw];
#pragma unroll
                    for (int pw = 0; pw < 4; pw++)
                        fma2(acc[oc][pw], P[2 * pw + kw], w2);
                }
        }
        __syncthreads();
    }

#pragma unroll
    for (int oc = 0; oc < 4; oc++) {
        float bv = bias[oc0 + oc];
        float* obase = out + ((size_t)(n * COUT + oc0 + oc)) * HOUT * HOUT +
                       (size_t)(r0 + loh0) * HOUT + (c0 + low0);
#pragma unroll
        for (int pw = 0; pw < 4; pw++) {
            float2 v = unpk(acc[oc][pw]);
            v.x += bv; v.y += bv;
            if (POST) { v.x = fmaxf(v.x, 0.f); v.y = fmaxf(v.y, 0.f); }
            obase[pw]        = v.x;
            obase[HOUT + pw] = v.y;
        }
    }
}

// ---------------------------------------------------------------------------
// ConvTranspose2d k=4 s=2 p=1 (torch layout (CIN,COUT,4,4)), f32x2 packed.
// Lanes = (oh even, oh odd). For a fixed input column iw and kw tap, the two
// output rows consume rows {ih0,ih0+1} (kh 1/0) and {ih0-1,ih0} (kh 3/2), so
// weights are pre-paired {w[kh_odd],w[kh_even]} in smem.
// grid(COUT/OCB, (HOUT/32)^2, B), block 128.
// ---------------------------------------------------------------------------
template<int CIN, int COUT, int OCB, int HIN, int HOUT, bool PRE, bool POST>
__global__ void __launch_bounds__(128, 4) convT4x4s2_k(
    const float* __restrict__ in, const float* __restrict__ w,
    const float* __restrict__ bias, float* __restrict__ out)
{
    const int n   = blockIdx.z;
    const int oc0 = blockIdx.x * OCB;
    const int TB  = HOUT / 32;
    const int r0  = (blockIdx.y / TB) * 32;
    const int c0  = (blockIdx.y % TB) * 32;
    const int tid = threadIdx.x;
    const int loh0 = (tid >> 3) * 2;
    const int low0 = (tid & 7) * 4;

    __shared__ float s_in[2][18 * 18];
    __shared__ ull   s_w2[CIN * OCB * 8];   // [ci][oc][kw][pair]

    // preload paired weights: pair0 = {w[1][kw], w[0][kw]}, pair1 = {w[3][kw], w[2][kw]}
    for (int i = tid; i < CIN * OCB * 8; i += 128) {
        int per = OCB * 8;
        int ci = i / per;
        int r  = i - ci * per;
        int oc = r >> 3;
        int t  = r & 7;
        int kw = t >> 1, p = t & 1;
        const float* wb = w + ((size_t)ci * COUT + oc0 + oc) * 16;
        s_w2[i] = pk2(wb[(p * 2 + 1) * 4 + kw], wb[(p * 2) * 4 + kw]);
    }

    const int ihb = (r0 - 2) / 2;
    const int iwb = (c0 - 2) / 2;
    const float* inp = in + (size_t)n * CIN * HIN * HIN;

    int goff[3];
#pragma unroll
    for (int s = 0; s < 3; s++) {
        int idx = tid + s * 128;
        int r = idx / 18, c = idx - r * 18;
        int ih = ihb + r, iw = iwb + c;
        goff[s] = ((unsigned)ih < (unsigned)HIN && (unsigned)iw < (unsigned)HIN)
                      ? ih * HIN + iw : -1;
    }

    // stage ci = 0
    {
        float* b0 = s_in[0];
#pragma unroll
        for (int s = 0; s < 2; s++) {
            float v = (goff[s] >= 0) ? inp[goff[s]] : 0.f;
            if (PRE) v = fmaxf(v, 0.f);
            b0[tid + s * 128] = v;
        }
        if (tid < 68) {
            float v = (goff[2] >= 0) ? inp[goff[2]] : 0.f;
            if (PRE) v = fmaxf(v, 0.f);
            b0[tid + 256] = v;
        }
    }
    __syncthreads();

    ull acc[OCB][4];
#pragma unroll
    for (int a = 0; a < OCB; a++)
#pragma unroll
        for (int q = 0; q < 4; q++) acc[a][q] = 0ULL;

    const int rb = loh0 >> 1;   // local row of ih0-1
    const int cb = low0 >> 1;   // local col base

    for (int ci = 0; ci < CIN; ci++) {
        const float* cur = s_in[ci & 1];
        if (ci + 1 < CIN) {
            const float* inn = inp + (size_t)(ci + 1) * HIN * HIN;
            float* nb = s_in[(ci + 1) & 1];
#pragma unroll
            for (int s = 0; s < 2; s++) {
                float v = (goff[s] >= 0) ? inn[goff[s]] : 0.f;
                if (PRE) v = fmaxf(v, 0.f);
                nb[tid + s * 128] = v;
            }
            if (tid < 68) {
                float v = (goff[2] >= 0) ? inn[goff[2]] : 0.f;
                if (PRE) v = fmaxf(v, 0.f);
                nb[tid + 256] = v;
            }
        }

        // rows ih0-1, ih0, ih0+1 at 4 columns
        ull A[4], B[4];
#pragma unroll
        for (int c = 0; c < 4; c++) {
            float x0 = cur[rb * 18 + cb + c];
            float x1 = cur[(rb + 1) * 18 + cb + c];
            float x2 = cur[(rb + 2) * 18 + cb + c];
            A[c] = pk2(x1, x2);   // lanes: (ph0 uses ih0 w/ kh1, ph1 uses ih0+1 w/ kh0)
            B[c] = pk2(x0, x1);   // lanes: (ph0 uses ih0-1 w/ kh3, ph1 uses ih0 w/ kh2)
        }

        const ull* wci = s_w2 + ci * OCB * 8;
#pragma unroll
        for (int oc = 0; oc < OCB; oc++) {
            const ull* wp = wci + oc * 8;
#pragma unroll
            for (int pw = 0; pw < 4; pw++) {
                const int kwh = (pw & 1) ? 0 : 1;
                const int rh  = (pw >> 1) + 1 + (pw & 1);
                fma2(acc[oc][pw], A[rh],     wp[kwh * 2 + 0]);
                fma2(acc[oc][pw], B[rh],     wp[kwh * 2 + 1]);
                fma2(acc[oc][pw], A[rh - 1], wp[(kwh + 2) * 2 + 0]);
                fma2(acc[oc][pw], B[rh - 1], wp[(kwh + 2) * 2 + 1]);
            }
        }
        __syncthreads();
    }

#pragma unroll
    for (int oc = 0; oc < OCB; oc++) {
        float bv = bias[oc0 + oc];
        float* obase = out + ((size_t)(n * COUT + oc0 + oc)) * HOUT * HOUT +
                       (size_t)(r0 + loh0) * HOUT + (c0 + low0);
#pragma unroll
        for (int pw = 0; pw < 4; pw++) {
            float2 v = unpk(acc[oc][pw]);
            v.x += bv; v.y += bv;
            if (POST) { v.x = fmaxf(v.x, 0.f); v.y = fmaxf(v.y, 0.f); }
            obase[pw]        = v.x;   // oh even
            obase[HOUT + pw] = v.y;   // oh odd
        }
    }
}

// ---------------------------------------------------------------------------
// 1x1 conv on 32x32 images (unchanged from passing round).
// ---------------------------------------------------------------------------
template<int CIN, int COUT, bool PRE, bool BIAS, bool ADDRES>
__global__ void __launch_bounds__(256) conv1x1_k(
    const float* __restrict__ in, const float* __restrict__ w,
    const float* __restrict__ bias, float* __restrict__ out)
{
    const int n   = blockIdx.y;
    const int oc0 = blockIdx.x * 4;
    const int tid = threadIdx.x;
    const int hw0 = tid * 4;

    __shared__ float s_w[4 * CIN];
    for (int i = tid; i < 4 * CIN; i += 256)
        s_w[i] = w[(oc0 + i / CIN) * CIN + (i % CIN)];
    __syncthreads();

    float acc[4][4];
#pragma unroll
    for (int a = 0; a < 4; a++)
#pragma unroll
        for (int q = 0; q < 4; q++) acc[a][q] = 0.f;

    const float* inp = in + (size_t)n * CIN * 1024 + hw0;
    for (int ci = 0; ci < CIN; ci++) {
        float4 v = *reinterpret_cast<const float4*>(inp + (size_t)ci * 1024);
        if (PRE) {
            v.x = fmaxf(v.x, 0.f); v.y = fmaxf(v.y, 0.f);
            v.z = fmaxf(v.z, 0.f); v.w = fmaxf(v.w, 0.f);
        }
#pragma unroll
        for (int oc = 0; oc < 4; oc++) {
            float wv = s_w[oc * CIN + ci];
            acc[oc][0] = fmaf(v.x, wv, acc[oc][0]);
            acc[oc][1] = fmaf(v.y, wv, acc[oc][1]);
            acc[oc][2] = fmaf(v.z, wv, acc[oc][2]);
            acc[oc][3] = fmaf(v.w, wv, acc[oc][3]);
        }
    }

#pragma unroll
    for (int oc = 0; oc < 4; oc++) {
        float bv = BIAS ? bias[oc0 + oc] : 0.f;
        float* op = out + ((size_t)(n * COUT + oc0 + oc)) * 1024 + hw0;
        float4 o;
        o.x = acc[oc][0] + bv; o.y = acc[oc][1] + bv;
        o.z = acc[oc][2] + bv; o.w = acc[oc][3] + bv;
        if (ADDRES) {
            float4 r = *reinterpret_cast<const float4*>(op);
            o.x += r.x; o.y += r.y; o.z += r.z; o.w += r.w;
        }
        *reinterpret_cast<float4*>(op) = o;
    }
}

// ---------------------------------------------------------------------------
// Vector quantizer (unchanged from passing round).
// ---------------------------------------------------------------------------
#define VQ_SMEM ((32768 + 512 + 512 + 256) * 4)

__global__ void __launch_bounds__(256) vq_k(
    const float* __restrict__ ze, const float* __restrict__ E,
    float* __restrict__ zq, int* __restrict__ hist, float* __restrict__ mse)
{
    extern __shared__ float sm[];
    float* sE   = sm;
    float* sEsq = sm + 32768;
    int*   sHist= (int*)(sm + 33280);
    float* sRed = sm + 33792;

    const int tid = threadIdx.x;
    for (int i = tid; i < VQ_K * VQ_D; i += 256) sE[i] = E[i];
    for (int i = tid; i < VQ_K; i += 256) sHist[i] = 0;
    __syncthreads();
    for (int i = tid; i < VQ_K; i += 256) {
        const float* e = &sE[i * VQ_D];
        float s = 0.f;
#pragma unroll 16
        for (int d = 0; d < VQ_D; d++) s = fmaf(e[d], e[d], s);
        sEsq[i] = s;
    }
    __syncthreads();

    const int p  = blockIdx.x * 256 + tid;
    const int n  = p >> 10;
    const int hw = p & 1023;
    const float* zp = ze + (size_t)n * VQ_D * 1024 + hw;

    float f[VQ_D];
#pragma unroll
    for (int d = 0; d < VQ_D; d++) f[d] = zp[(size_t)d * 1024];

    float best = 3.4e38f;
    int   bi   = 0;
    for (int k = 0; k < VQ_K; k++) {
        const float4* e4 = reinterpret_cast<const float4*>(&sE[k * VQ_D]);
        float s0 = 0.f, s1 = 0.f, s2 = 0.f, s3 = 0.f;
#pragma unroll
        for (int d = 0; d < VQ_D / 4; d++) {
            float4 e = e4[d];
            s0 = fmaf(e.x, f[4 * d + 0], s0);
            s1 = fmaf(e.y, f[4 * d + 1], s1);
            s2 = fmaf(e.z, f[4 * d + 2], s2);
            s3 = fmaf(e.w, f[4 * d + 3], s3);
        }
        float score = sEsq[k] - 2.f * ((s0 + s1) + (s2 + s3));
        if (score < best) { best = score; bi = k; }
    }

    const float* eb = &sE[bi * VQ_D];
    float* zqp = zq + (size_t)n * VQ_D * 1024 + hw;
    float md = 0.f;
#pragma unroll
    for (int d = 0; d < VQ_D; d++) {
        float ev = eb[d];
        float dd = f[d] - ev;
        md = fmaf(dd, dd, md);
        zqp[(size_t)d * 1024] = ev;
    }

    atomicAdd(&sHist[bi], 1);
    sRed[tid] = md;
    __syncthreads();
    for (int s = 128; s > 0; s >>= 1) {
        if (tid < s) sRed[tid] += sRed[tid + s];
        __syncthreads();
    }
    if (tid == 0) atomicAdd(mse, sRed[0]);
    for (int i = tid; i < VQ_K; i += 256) {
        int c = sHist[i];
        if (c) atomicAdd(&hist[i], c);
    }
}

__global__ void finalize_k(const int* __restrict__ hist,
                           const float* __restrict__ mse,
                           float* __restrict__ out)
{
    __shared__ float red[VQ_K];
    const int k = threadIdx.x;
    float pb = (float)hist[k] * (1.f / 65536.f);
    red[k] = pb * log2f(pb + 1e-10f);
    __syncthreads();
    for (int s = 256; s > 0; s >>= 1) {
        if (k < s) red[k] += red[k + s];
        __syncthreads();
    }
    if (k == 0) {
        float H = -red[0];
        float m = mse[0] * (1.f / (65536.f * 64.f));
        out[0]       = 1.25f * m;
        out[OUT_ELQ] = m;
        out[OUT_QLQ] = m;
        out[OUT_EW]  = exp2f(H);
    }
}

// ---------------------------------------------------------------------------
// Launch
// ---------------------------------------------------------------------------
extern "C" void kernel_launch(void* const* d_in, const int* in_sizes, int n_in,
                              void* d_out, int out_size)
{
    (void)in_sizes; (void)n_in; (void)out_size;
    const float* x          = (const float*)d_in[0];
    const float* enc_w1     = (const float*)d_in[1];
    const float* enc_b1     = (const float*)d_in[2];
    const float* enc_w2     = (const float*)d_in[3];
    const float* enc_b2     = (const float*)d_in[4];
    const float* enc_w3     = (const float*)d_in[5];
    const float* enc_b3     = (const float*)d_in[6];
    const float* enc_w4     = (const float*)d_in[7];
    const float* enc_b4     = (const float*)d_in[8];
    const float* enc_res_w1 = (const float*)d_in[9];
    const float* enc_res_w2 = (const float*)d_in[10];
    const float* enc_adj_w  = (const float*)d_in[11];
    const float* enc_adj_b  = (const float*)d_in[12];
    const float* E          = (const float*)d_in[13];
    const float* dec_adj_w  = (const float*)d_in[14];
    const float* dec_adj_b  = (const float*)d_in[15];
    const float* dec_res_w1 = (const float*)d_in[16];
    const float* dec_res_w2 = (const float*)d_in[17];
    const float* tc1_w      = (const float*)d_in[18];
    const float* tc1_b      = (const float*)d_in[19];
    const float* tc2_w      = (const float*)d_in[20];
    const float* tc2_b      = (const float*)d_in[21];
    float* out = (float*)d_out;

    float *h1, *a, *b, *mid, *ze, *zq, *mse; int* hist;
    cudaGetSymbolAddress((void**)&h1,  g_h1);
    cudaGetSymbolAddress((void**)&a,   g_a);
    cudaGetSymbolAddress((void**)&b,   g_b);
    cudaGetSymbolAddress((void**)&mid, g_mid);
    cudaGetSymbolAddress((void**)&ze,  g_ze);
    cudaGetSymbolAddress((void**)&zq,  g_zq);
    cudaGetSymbolAddress((void**)&mse, g_mse);
    cudaGetSymbolAddress((void**)&hist, g_hist);

    cudaFuncSetAttribute(vq_k, cudaFuncAttributeMaxDynamicSharedMemorySize, VQ_SMEM);

    const int SMEM_C1 = 3  * 4 * 16 * 8 + 2 * 66 * 66 * 4;   // 36384
    const int SMEM_C2 = 64 * 4 * 16 * 8 + 2 * 66 * 66 * 4;   // 67616
    cudaFuncSetAttribute(conv4x4s2_k<3, 64, 128, 64, true>,
                         cudaFuncAttributeMaxDynamicSharedMemorySize, SMEM_C1);
    cudaFuncSetAttribute(conv4x4s2_k<64, 128, 64, 32, true>,
                         cudaFuncAttributeMaxDynamicSharedMemorySize, SMEM_C2);

    reset_k<<<1, 512>>>(hist, mse);

    // ---- Encoder ----
    conv4x4s2_k<3, 64, 128, 64, true><<<dim3(16, 4, BATCH), 128, SMEM_C1>>>(x, enc_w1, enc_b1, h1);
    conv4x4s2_k<64, 128, 64, 32, true><<<dim3(32, 1, BATCH), 128, SMEM_C2>>>(h1, enc_w2, enc_b2, a);
    conv3x3_k<128, 128, false, true,  true><<<dim3(32, BATCH), 128>>>(a, enc_w3, enc_b3, b);
    conv3x3_k<128, 128, false, false, true><<<dim3(32, BATCH), 128>>>(b, enc_w4, enc_b4, a);
    conv3x3_k<128, 64, true, true, false><<<dim3(16, BATCH), 128>>>(a, enc_res_w1, nullptr, mid);
    conv1x1_k<64, 128, false, false, true><<<dim3(32, BATCH), 256>>>(mid, enc_res_w2, nullptr, a);
    conv3x3_k<128, 64, true, true, false><<<dim3(16, BATCH), 128>>>(a, enc_res_w1 + 64 * 128 * 9, nullptr, mid);
    conv1x1_k<64, 128, false, false, true><<<dim3(32, BATCH), 256>>>(mid, enc_res_w2 + 128 * 64, nullptr, a);
    conv1x1_k<128, 64, true, true, false><<<dim3(16, BATCH), 256>>>(a, enc_adj_w, enc_adj_b, ze);

    // ---- Vector quantizer ----
    vq_k<<<256, 256, VQ_SMEM>>>(ze, E, zq, hist, mse);
    finalize_k<<<1, 512>>>(hist, mse, out);

    // ---- Decoder ----
    conv3x3_k<64, 128, false, false, true><<<dim3(32, BATCH), 128>>>(zq, dec_adj_w, dec_adj_b, a);
    conv3x3_k<128, 64, true, true, false><<<dim3(16, BATCH), 128>>>(a, dec_res_w1, nullptr, mid);
    conv1x1_k<64, 128, false, false, true><<<dim3(32, BATCH), 256>>>(mid, dec_res_w2, nullptr, a);
    conv3x3_k<128, 64, true, true, false><<<dim3(16, BATCH), 128>>>(a, dec_res_w1 + 64 * 128 * 9, nullptr, mid);
    conv1x1_k<64, 128, false, false, true><<<dim3(32, BATCH), 256>>>(mid, dec_res_w2 + 128 * 64, nullptr, a);
    convT4x4s2_k<128, 64, 4, 32, 64, true, true><<<dim3(16, 4, BATCH), 128>>>(a, tc1_w, tc1_b, h1);
    convT4x4s2_k<64, 3, 3, 64, 128, false, false><<<dim3(1, 16, BATCH), 128>>>(h1, tc2_w, tc2_b, out + OUT_RECON_OFF);
}